// round 1
// baseline (speedup 1.0000x reference)
#include <cuda_runtime.h>
#include <math.h>

// Problem constants
#define B_ 8
#define C_ 128
#define N_ 2048
#define K2C 256
#define KSPLIT 16
#define SLOPE 0.2f

// ---------------- device scratch (allocation-free) ----------------
__device__ float g_epart[KSPLIT * B_ * C_ * C_];   // 8 MB  partial energy
__device__ float g_att[B_ * C_ * C_];              // attention
__device__ float g_xglb[B_ * C_ * N_];             // 8 MB  gamma*out + x
__device__ float g_adj[(size_t)B_ * N_ * N_];      // 134 MB dynamic adjacency
__device__ float g_y1[B_ * C_ * N_];               // 8 MB  leaky(x @ adj)

// ---------------- shared GEMM micro-kernel helpers ----------------
// Transposed A staging: As[t][m] = A[m][kk+t]  (A row-major, k contiguous)
__device__ __forceinline__ void load_a_trans(float As[8][128],
                                             const float* __restrict__ A,
                                             int lda, int kk, int tid) {
    int m = tid & 127;
    int j = tid >> 7;  // 0 or 1 -> which float4 of the 8-wide k chunk
    float4 v = *reinterpret_cast<const float4*>(A + m * lda + kk + j * 4);
    As[j * 4 + 0][m] = v.x;
    As[j * 4 + 1][m] = v.y;
    As[j * 4 + 2][m] = v.z;
    As[j * 4 + 3][m] = v.w;
}

// Direct B staging: Bs[t][n] = Brow[t*ldb + n]  (n contiguous)
__device__ __forceinline__ void load_b_rows(float Bs[8][128],
                                            const float* __restrict__ Brow,
                                            int ldb, int tid) {
    int t = tid >> 5;
    int nc = (tid & 31) << 2;
    *reinterpret_cast<float4*>(&Bs[t][nc]) =
        *reinterpret_cast<const float4*>(Brow + t * ldb + nc);
}

// 8 k-steps of 8x8 outer product per thread
__device__ __forceinline__ void mm8(const float As[8][128], const float Bs[8][128],
                                    float acc[8][8], int ty, int tx) {
#pragma unroll
    for (int t = 0; t < 8; ++t) {
        float4 a0 = *reinterpret_cast<const float4*>(&As[t][ty * 8]);
        float4 a1 = *reinterpret_cast<const float4*>(&As[t][ty * 8 + 4]);
        float4 b0 = *reinterpret_cast<const float4*>(&Bs[t][tx * 8]);
        float4 b1 = *reinterpret_cast<const float4*>(&Bs[t][tx * 8 + 4]);
        float a[8] = {a0.x, a0.y, a0.z, a0.w, a1.x, a1.y, a1.z, a1.w};
        float b[8] = {b0.x, b0.y, b0.z, b0.w, b1.x, b1.y, b1.z, b1.w};
#pragma unroll
        for (int i = 0; i < 8; ++i)
#pragma unroll
            for (int j = 0; j < 8; ++j)
                acc[i][j] = fmaf(a[i], b[j], acc[i][j]);
    }
}

__device__ __forceinline__ float leaky(float v) {
    return v > 0.0f ? v : SLOPE * v;
}

// ---------------- kernel 1: energy partials ----------------
// E_part[ks][b][c][d] = sum_{k in chunk ks} x[b,c,k] * x[b,d,k]
__global__ void __launch_bounds__(256) k_energy(const float* __restrict__ x) {
    __shared__ float S[8][128];  // A == B (symmetric)
    int b = blockIdx.x, ks = blockIdx.y;
    int tid = threadIdx.x, ty = tid >> 4, tx = tid & 15;
    const float* A = x + b * C_ * N_ + ks * (N_ / KSPLIT);
    float acc[8][8] = {};
    for (int kk = 0; kk < N_ / KSPLIT; kk += 8) {
        __syncthreads();
        load_a_trans(S, A, N_, kk, tid);
        __syncthreads();
        mm8(S, S, acc, ty, tx);
    }
    float* out = g_epart + ((ks * B_ + b) * C_) * C_;
#pragma unroll
    for (int i = 0; i < 8; ++i) {
        int r = ty * 8 + i;
        float4 v0 = make_float4(acc[i][0], acc[i][1], acc[i][2], acc[i][3]);
        float4 v1 = make_float4(acc[i][4], acc[i][5], acc[i][6], acc[i][7]);
        *reinterpret_cast<float4*>(out + r * C_ + tx * 8) = v0;
        *reinterpret_cast<float4*>(out + r * C_ + tx * 8 + 4) = v1;
    }
}

// ---------------- kernel 2: reduce partials + softmax(-energy) ----------------
// softmax(rowmax - e) == softmax(-e)
__global__ void __launch_bounds__(128) k_softmax() {
    int warp = threadIdx.x >> 5, lane = threadIdx.x & 31;
    int row = blockIdx.x * 4 + warp;  // 0..1023
    int b = row >> 7, c = row & 127;
    float e[4];
#pragma unroll
    for (int q = 0; q < 4; ++q) {
        int d = lane + q * 32;
        float s = 0.0f;
#pragma unroll
        for (int p = 0; p < KSPLIT; ++p)
            s += g_epart[((p * B_ + b) * C_ + c) * C_ + d];
        e[q] = -s;  // negated energy
    }
    float m = fmaxf(fmaxf(e[0], e[1]), fmaxf(e[2], e[3]));
#pragma unroll
    for (int off = 16; off > 0; off >>= 1)
        m = fmaxf(m, __shfl_xor_sync(0xffffffffu, m, off));
    float p4[4], s = 0.0f;
#pragma unroll
    for (int q = 0; q < 4; ++q) {
        p4[q] = __expf(e[q] - m);
        s += p4[q];
    }
#pragma unroll
    for (int off = 16; off > 0; off >>= 1)
        s += __shfl_xor_sync(0xffffffffu, s, off);
    float inv = 1.0f / s;
#pragma unroll
    for (int q = 0; q < 4; ++q)
        g_att[(b * C_ + c) * C_ + lane + q * 32] = p4[q] * inv;
}

// ---------------- kernel 3: x_glb = gamma * (att @ x) + x ----------------
__global__ void __launch_bounds__(256) k_xglb(const float* __restrict__ x,
                                              const float* __restrict__ gamma) {
    __shared__ float As[8][128], Bs[8][128];
    int nt = blockIdx.x, b = blockIdx.y;
    int tid = threadIdx.x, ty = tid >> 4, tx = tid & 15;
    int n0 = nt * 128;
    const float* A = g_att + b * C_ * C_;
    const float* Bbase = x + b * C_ * N_ + n0;
    float acc[8][8] = {};
    for (int kk = 0; kk < C_; kk += 8) {
        __syncthreads();
        load_a_trans(As, A, C_, kk, tid);
        load_b_rows(Bs, Bbase + kk * N_, N_, tid);
        __syncthreads();
        mm8(As, Bs, acc, ty, tx);
    }
    float gm = *gamma;
    float* out = g_xglb + b * C_ * N_ + n0;
    const float* xr = x + b * C_ * N_ + n0;
#pragma unroll
    for (int i = 0; i < 8; ++i) {
        int r = ty * 8 + i;
        float4 xv0 = *reinterpret_cast<const float4*>(xr + r * N_ + tx * 8);
        float4 xv1 = *reinterpret_cast<const float4*>(xr + r * N_ + tx * 8 + 4);
        float4 v0 = make_float4(fmaf(gm, acc[i][0], xv0.x), fmaf(gm, acc[i][1], xv0.y),
                                fmaf(gm, acc[i][2], xv0.z), fmaf(gm, acc[i][3], xv0.w));
        float4 v1 = make_float4(fmaf(gm, acc[i][4], xv1.x), fmaf(gm, acc[i][5], xv1.y),
                                fmaf(gm, acc[i][6], xv1.z), fmaf(gm, acc[i][7], xv1.w));
        *reinterpret_cast<float4*>(out + r * N_ + tx * 8) = v0;
        *reinterpret_cast<float4*>(out + r * N_ + tx * 8 + 4) = v1;
    }
}

// ---------------- kernel 4: adj = sigmoid(w_adj @ [x_glb; x] + b_adj) ----------------
__global__ void __launch_bounds__(256) k_adj(const float* __restrict__ x,
                                             const float* __restrict__ w_adj,
                                             const float* __restrict__ b_adj) {
    __shared__ float As[8][128], Bs[8][128];
    int nt = blockIdx.x, mt = blockIdx.y, b = blockIdx.z;
    int tid = threadIdx.x, ty = tid >> 4, tx = tid & 15;
    int m0 = mt * 128, n0 = nt * 128;
    const float* A = w_adj + m0 * K2C;
    float acc[8][8] = {};
    for (int kk = 0; kk < K2C; kk += 8) {
        const float* Bbase = (kk < C_)
            ? (g_xglb + b * C_ * N_ + kk * N_ + n0)
            : (x + b * C_ * N_ + (kk - C_) * N_ + n0);
        __syncthreads();
        load_a_trans(As, A, K2C, kk, tid);
        load_b_rows(Bs, Bbase, N_, tid);
        __syncthreads();
        mm8(As, Bs, acc, ty, tx);
    }
    float* out = g_adj + (size_t)b * N_ * N_ + (size_t)m0 * N_ + n0;
#pragma unroll
    for (int i = 0; i < 8; ++i) {
        int r = ty * 8 + i;
        float bias = b_adj[m0 + r];
        float4 v0, v1;
        v0.x = 1.0f / (1.0f + __expf(-(acc[i][0] + bias)));
        v0.y = 1.0f / (1.0f + __expf(-(acc[i][1] + bias)));
        v0.z = 1.0f / (1.0f + __expf(-(acc[i][2] + bias)));
        v0.w = 1.0f / (1.0f + __expf(-(acc[i][3] + bias)));
        v1.x = 1.0f / (1.0f + __expf(-(acc[i][4] + bias)));
        v1.y = 1.0f / (1.0f + __expf(-(acc[i][5] + bias)));
        v1.z = 1.0f / (1.0f + __expf(-(acc[i][6] + bias)));
        v1.w = 1.0f / (1.0f + __expf(-(acc[i][7] + bias)));
        *reinterpret_cast<float4*>(out + (size_t)r * N_ + tx * 8) = v0;
        *reinterpret_cast<float4*>(out + (size_t)r * N_ + tx * 8 + 4) = v1;
    }
}

// ---------------- kernel 5: y1 = leaky(x @ adj) ----------------
__global__ void __launch_bounds__(256) k_y1(const float* __restrict__ x) {
    __shared__ float As[8][128], Bs[8][128];
    int nt = blockIdx.x, b = blockIdx.y;
    int tid = threadIdx.x, ty = tid >> 4, tx = tid & 15;
    int n0 = nt * 128;
    const float* A = x + b * C_ * N_;                       // [C, N] k contiguous
    const float* Bbase = g_adj + (size_t)b * N_ * N_ + n0;  // rows k, n contiguous
    float acc[8][8] = {};
    for (int kk = 0; kk < N_; kk += 8) {
        __syncthreads();
        load_a_trans(As, A, N_, kk, tid);
        load_b_rows(Bs, Bbase + (size_t)kk * N_, N_, tid);
        __syncthreads();
        mm8(As, Bs, acc, ty, tx);
    }
    float* out = g_y1 + b * C_ * N_ + n0;
#pragma unroll
    for (int i = 0; i < 8; ++i) {
        int r = ty * 8 + i;
        float4 v0 = make_float4(leaky(acc[i][0]), leaky(acc[i][1]),
                                leaky(acc[i][2]), leaky(acc[i][3]));
        float4 v1 = make_float4(leaky(acc[i][4]), leaky(acc[i][5]),
                                leaky(acc[i][6]), leaky(acc[i][7]));
        *reinterpret_cast<float4*>(out + r * N_ + tx * 8) = v0;
        *reinterpret_cast<float4*>(out + r * N_ + tx * 8 + 4) = v1;
    }
}

// ---------------- kernel 6: y = leaky(w_dyn @ y1 + b_dyn) ----------------
__global__ void __launch_bounds__(256) k_y2(const float* __restrict__ w_dyn,
                                            const float* __restrict__ b_dyn,
                                            float* __restrict__ out) {
    __shared__ float As[8][128], Bs[8][128];
    int nt = blockIdx.x, b = blockIdx.y;
    int tid = threadIdx.x, ty = tid >> 4, tx = tid & 15;
    int n0 = nt * 128;
    const float* Bbase = g_y1 + b * C_ * N_ + n0;
    float acc[8][8] = {};
    for (int kk = 0; kk < C_; kk += 8) {
        __syncthreads();
        load_a_trans(As, w_dyn, C_, kk, tid);
        load_b_rows(Bs, Bbase + kk * N_, N_, tid);
        __syncthreads();
        mm8(As, Bs, acc, ty, tx);
    }
    float* o = out + b * C_ * N_ + n0;
#pragma unroll
    for (int i = 0; i < 8; ++i) {
        int r = ty * 8 + i;
        float bias = b_dyn[r];
        float4 v0 = make_float4(leaky(acc[i][0] + bias), leaky(acc[i][1] + bias),
                                leaky(acc[i][2] + bias), leaky(acc[i][3] + bias));
        float4 v1 = make_float4(leaky(acc[i][4] + bias), leaky(acc[i][5] + bias),
                                leaky(acc[i][6] + bias), leaky(acc[i][7] + bias));
        *reinterpret_cast<float4*>(o + r * N_ + tx * 8) = v0;
        *reinterpret_cast<float4*>(o + r * N_ + tx * 8 + 4) = v1;
    }
}

// ---------------- launch ----------------
extern "C" void kernel_launch(void* const* d_in, const int* in_sizes, int n_in,
                              void* d_out, int out_size) {
    const float* x      = (const float*)d_in[0];  // [8,128,2048]
    const float* w_adj  = (const float*)d_in[1];  // [2048,256]
    const float* b_adj  = (const float*)d_in[2];  // [2048]
    const float* w_dyn  = (const float*)d_in[3];  // [128,128]
    const float* b_dyn  = (const float*)d_in[4];  // [128]
    const float* gamma  = (const float*)d_in[5];  // [1]
    float* out = (float*)d_out;                   // [8,128,2048]

    k_energy<<<dim3(B_, KSPLIT), 256>>>(x);
    k_softmax<<<256, 128>>>();
    k_xglb<<<dim3(N_ / 128, B_), 256>>>(x, gamma);
    k_adj<<<dim3(N_ / 128, N_ / 128, B_), 256>>>(x, w_adj, b_adj);
    k_y1<<<dim3(N_ / 128, B_), 256>>>(x);
    k_y2<<<dim3(N_ / 128, B_), 256>>>(w_dyn, b_dyn, out);
}

// round 2
// speedup vs baseline: 1.2942x; 1.2942x over previous
#include <cuda_runtime.h>
#include <math.h>

// Problem constants
#define B_ 8
#define C_ 128
#define N_ 2048
#define K2C 256
#define KSPLIT 16
#define SLOPE 0.2f

typedef unsigned long long u64;

// ---------------- device scratch (allocation-free) ----------------
__device__ float g_epart[KSPLIT * B_ * C_ * C_];   // partial energy
__device__ float g_att[B_ * C_ * C_];              // attention
__device__ float g_xglb[B_ * C_ * N_];             // gamma*out + x
__device__ float g_adj[(size_t)B_ * N_ * N_];      // 134 MB dynamic adjacency
__device__ float g_y1[B_ * C_ * N_];               // leaky(x @ adj)

// ---------------- f32x2 packed math ----------------
__device__ __forceinline__ u64 pack2(float x, float y) {
    u64 r;
    asm("mov.b64 %0, {%1, %2};" : "=l"(r) : "f"(x), "f"(y));
    return r;
}
__device__ __forceinline__ float2 unpack2(u64 v) {
    float2 r;
    asm("mov.b64 {%0, %1}, %2;" : "=f"(r.x), "=f"(r.y) : "l"(v));
    return r;
}
__device__ __forceinline__ void ffma2(u64& d, u64 a, u64 b) {
    asm("fma.rn.f32x2 %0, %1, %2, %0;" : "+l"(d) : "l"(a), "l"(b));
}

// ---------------- staging helpers ----------------
// A (row-major, k contiguous): stage transposed As[t][m] = A[m][kk+t]
__device__ __forceinline__ float4 lda_g(const float* __restrict__ A, int lda,
                                        int kk, int tid) {
    int m = tid & 127, j = tid >> 7;
    return *reinterpret_cast<const float4*>(A + m * lda + kk + j * 4);
}
__device__ __forceinline__ void sta_s(float As[8][128], float4 v, int tid) {
    int m = tid & 127, j = tid >> 7;
    As[j * 4 + 0][m] = v.x;
    As[j * 4 + 1][m] = v.y;
    As[j * 4 + 2][m] = v.z;
    As[j * 4 + 3][m] = v.w;
}
// B (rows of k, n contiguous): Bs[t][n] = Brow[t*ldb + n]
__device__ __forceinline__ float4 ldb_g(const float* __restrict__ Brow, int ldb,
                                        int tid) {
    int t = tid >> 5, nc = (tid & 31) << 2;
    return *reinterpret_cast<const float4*>(Brow + t * ldb + nc);
}
__device__ __forceinline__ void stb_s(float Bs[8][128], float4 v, int tid) {
    int t = tid >> 5, nc = (tid & 31) << 2;
    *reinterpret_cast<float4*>(&Bs[t][nc]) = v;
}

// 8 k-steps of 8x8 outer product per thread, packed f32x2 accumulators
__device__ __forceinline__ void mm8(const float As[8][128], const float Bs[8][128],
                                    u64 acc[8][4], int ty, int tx) {
#pragma unroll
    for (int t = 0; t < 8; ++t) {
        float4 a0 = *reinterpret_cast<const float4*>(&As[t][ty * 8]);
        float4 a1 = *reinterpret_cast<const float4*>(&As[t][ty * 8 + 4]);
        const ulonglong2* bp = reinterpret_cast<const ulonglong2*>(&Bs[t][tx * 8]);
        ulonglong2 bA = bp[0], bB = bp[1];
        u64 b[4] = {bA.x, bA.y, bB.x, bB.y};
        float a[8] = {a0.x, a0.y, a0.z, a0.w, a1.x, a1.y, a1.z, a1.w};
#pragma unroll
        for (int i = 0; i < 8; ++i) {
            u64 ai = pack2(a[i], a[i]);
#pragma unroll
            for (int j = 0; j < 4; ++j) ffma2(acc[i][j], ai, b[j]);
        }
    }
}

__device__ __forceinline__ float leaky(float v) { return v > 0.0f ? v : SLOPE * v; }
__device__ __forceinline__ float sigm(float v) { return 1.0f / (1.0f + __expf(-v)); }

// ---------------- kernel 1: energy partials (A == B, symmetric) ----------------
__global__ void __launch_bounds__(256, 2) k_energy(const float* __restrict__ x) {
    __shared__ float S[2][8][128];
    int b = blockIdx.x, ks = blockIdx.y;
    int tid = threadIdx.x, ty = tid >> 4, tx = tid & 15;
    const float* A = x + b * C_ * N_ + ks * (N_ / KSPLIT);
    u64 acc[8][4] = {};
    float4 v = lda_g(A, N_, 0, tid);
    sta_s(S[0], v, tid);
    __syncthreads();
    int buf = 0;
    for (int kk = 8; kk < N_ / KSPLIT; kk += 8) {
        v = lda_g(A, N_, kk, tid);
        mm8(S[buf], S[buf], acc, ty, tx);
        sta_s(S[buf ^ 1], v, tid);
        __syncthreads();
        buf ^= 1;
    }
    mm8(S[buf], S[buf], acc, ty, tx);
    float* out = g_epart + ((ks * B_ + b) * C_) * C_;
#pragma unroll
    for (int i = 0; i < 8; ++i) {
        int r = ty * 8 + i;
        float2 c0 = unpack2(acc[i][0]), c1 = unpack2(acc[i][1]);
        float2 c2 = unpack2(acc[i][2]), c3 = unpack2(acc[i][3]);
        *reinterpret_cast<float4*>(out + r * C_ + tx * 8) =
            make_float4(c0.x, c0.y, c1.x, c1.y);
        *reinterpret_cast<float4*>(out + r * C_ + tx * 8 + 4) =
            make_float4(c2.x, c2.y, c3.x, c3.y);
    }
}

// ---------------- kernel 2: reduce partials + softmax(-energy) ----------------
__global__ void __launch_bounds__(128) k_softmax() {
    int warp = threadIdx.x >> 5, lane = threadIdx.x & 31;
    int row = blockIdx.x * 4 + warp;
    int b = row >> 7, c = row & 127;
    float e[4];
#pragma unroll
    for (int q = 0; q < 4; ++q) {
        int d = lane + q * 32;
        float s = 0.0f;
#pragma unroll
        for (int p = 0; p < KSPLIT; ++p)
            s += g_epart[((p * B_ + b) * C_ + c) * C_ + d];
        e[q] = -s;
    }
    float m = fmaxf(fmaxf(e[0], e[1]), fmaxf(e[2], e[3]));
#pragma unroll
    for (int off = 16; off > 0; off >>= 1)
        m = fmaxf(m, __shfl_xor_sync(0xffffffffu, m, off));
    float p4[4], s = 0.0f;
#pragma unroll
    for (int q = 0; q < 4; ++q) {
        p4[q] = __expf(e[q] - m);
        s += p4[q];
    }
#pragma unroll
    for (int off = 16; off > 0; off >>= 1)
        s += __shfl_xor_sync(0xffffffffu, s, off);
    float inv = 1.0f / s;
#pragma unroll
    for (int q = 0; q < 4; ++q)
        g_att[(b * C_ + c) * C_ + lane + q * 32] = p4[q] * inv;
}

// ---------------- kernel 3: x_glb = gamma * (att @ x) + x ----------------
__global__ void __launch_bounds__(256, 2) k_xglb(const float* __restrict__ x,
                                                 const float* __restrict__ gamma) {
    __shared__ float As[2][8][128], Bs[2][8][128];
    int nt = blockIdx.x, b = blockIdx.y;
    int tid = threadIdx.x, ty = tid >> 4, tx = tid & 15;
    int n0 = nt * 128;
    const float* A = g_att + b * C_ * C_;
    const float* Bbase = x + b * C_ * N_ + n0;
    u64 acc[8][4] = {};
    float4 va = lda_g(A, C_, 0, tid);
    float4 vb = ldb_g(Bbase, N_, tid);
    sta_s(As[0], va, tid);
    stb_s(Bs[0], vb, tid);
    __syncthreads();
    int buf = 0;
    for (int kk = 8; kk < C_; kk += 8) {
        va = lda_g(A, C_, kk, tid);
        vb = ldb_g(Bbase + kk * N_, N_, tid);
        mm8(As[buf], Bs[buf], acc, ty, tx);
        sta_s(As[buf ^ 1], va, tid);
        stb_s(Bs[buf ^ 1], vb, tid);
        __syncthreads();
        buf ^= 1;
    }
    mm8(As[buf], Bs[buf], acc, ty, tx);
    float gm = *gamma;
    float* out = g_xglb + b * C_ * N_ + n0;
    const float* xr = x + b * C_ * N_ + n0;
#pragma unroll
    for (int i = 0; i < 8; ++i) {
        int r = ty * 8 + i;
        float2 c0 = unpack2(acc[i][0]), c1 = unpack2(acc[i][1]);
        float2 c2 = unpack2(acc[i][2]), c3 = unpack2(acc[i][3]);
        float4 xv0 = *reinterpret_cast<const float4*>(xr + r * N_ + tx * 8);
        float4 xv1 = *reinterpret_cast<const float4*>(xr + r * N_ + tx * 8 + 4);
        float4 o0 = make_float4(fmaf(gm, c0.x, xv0.x), fmaf(gm, c0.y, xv0.y),
                                fmaf(gm, c1.x, xv0.z), fmaf(gm, c1.y, xv0.w));
        float4 o1 = make_float4(fmaf(gm, c2.x, xv1.x), fmaf(gm, c2.y, xv1.y),
                                fmaf(gm, c3.x, xv1.z), fmaf(gm, c3.y, xv1.w));
        *reinterpret_cast<float4*>(out + r * N_ + tx * 8) = o0;
        *reinterpret_cast<float4*>(out + r * N_ + tx * 8 + 4) = o1;
    }
}

// ---------------- kernel 4: adj = sigmoid(w_adj @ [x_glb; x] + b_adj) ----------------
__global__ void __launch_bounds__(256, 2) k_adj(const float* __restrict__ x,
                                                const float* __restrict__ w_adj,
                                                const float* __restrict__ b_adj) {
    __shared__ float As[2][8][128], Bs[2][8][128];
    int nt = blockIdx.x, mt = blockIdx.y, b = blockIdx.z;
    int tid = threadIdx.x, ty = tid >> 4, tx = tid & 15;
    int m0 = mt * 128, n0 = nt * 128;
    const float* A = w_adj + m0 * K2C;
    const float* Bg = g_xglb + b * C_ * N_ + n0;  // k in [0,128)
    const float* Bx = x + b * C_ * N_ + n0;       // k in [128,256)
    u64 acc[8][4] = {};
    float4 va = lda_g(A, K2C, 0, tid);
    float4 vb = ldb_g(Bg, N_, tid);
    sta_s(As[0], va, tid);
    stb_s(Bs[0], vb, tid);
    __syncthreads();
    int buf = 0;
    for (int kk = 8; kk < K2C; kk += 8) {
        const float* Bbase = (kk < C_) ? (Bg + kk * N_) : (Bx + (kk - C_) * N_);
        va = lda_g(A, K2C, kk, tid);
        vb = ldb_g(Bbase, N_, tid);
        mm8(As[buf], Bs[buf], acc, ty, tx);
        sta_s(As[buf ^ 1], va, tid);
        stb_s(Bs[buf ^ 1], vb, tid);
        __syncthreads();
        buf ^= 1;
    }
    mm8(As[buf], Bs[buf], acc, ty, tx);
    float* out = g_adj + (size_t)b * N_ * N_ + (size_t)m0 * N_ + n0;
#pragma unroll
    for (int i = 0; i < 8; ++i) {
        int r = ty * 8 + i;
        float bias = b_adj[m0 + r];
        float2 c0 = unpack2(acc[i][0]), c1 = unpack2(acc[i][1]);
        float2 c2 = unpack2(acc[i][2]), c3 = unpack2(acc[i][3]);
        float4 o0 = make_float4(sigm(c0.x + bias), sigm(c0.y + bias),
                                sigm(c1.x + bias), sigm(c1.y + bias));
        float4 o1 = make_float4(sigm(c2.x + bias), sigm(c2.y + bias),
                                sigm(c3.x + bias), sigm(c3.y + bias));
        *reinterpret_cast<float4*>(out + (size_t)r * N_ + tx * 8) = o0;
        *reinterpret_cast<float4*>(out + (size_t)r * N_ + tx * 8 + 4) = o1;
    }
}

// ---------------- kernel 5: y1 = leaky(x @ adj) ----------------
__global__ void __launch_bounds__(256, 2) k_y1(const float* __restrict__ x) {
    __shared__ float As[2][8][128], Bs[2][8][128];
    int nt = blockIdx.x, b = blockIdx.y;
    int tid = threadIdx.x, ty = tid >> 4, tx = tid & 15;
    int n0 = nt * 128;
    const float* A = x + b * C_ * N_;
    const float* Bbase = g_adj + (size_t)b * N_ * N_ + n0;
    u64 acc[8][4] = {};
    float4 va = lda_g(A, N_, 0, tid);
    float4 vb = ldb_g(Bbase, N_, tid);
    sta_s(As[0], va, tid);
    stb_s(Bs[0], vb, tid);
    __syncthreads();
    int buf = 0;
    for (int kk = 8; kk < N_; kk += 8) {
        va = lda_g(A, N_, kk, tid);
        vb = ldb_g(Bbase + (size_t)kk * N_, N_, tid);
        mm8(As[buf], Bs[buf], acc, ty, tx);
        sta_s(As[buf ^ 1], va, tid);
        stb_s(Bs[buf ^ 1], vb, tid);
        __syncthreads();
        buf ^= 1;
    }
    mm8(As[buf], Bs[buf], acc, ty, tx);
    float* out = g_y1 + b * C_ * N_ + n0;
#pragma unroll
    for (int i = 0; i < 8; ++i) {
        int r = ty * 8 + i;
        float2 c0 = unpack2(acc[i][0]), c1 = unpack2(acc[i][1]);
        float2 c2 = unpack2(acc[i][2]), c3 = unpack2(acc[i][3]);
        float4 o0 = make_float4(leaky(c0.x), leaky(c0.y), leaky(c1.x), leaky(c1.y));
        float4 o1 = make_float4(leaky(c2.x), leaky(c2.y), leaky(c3.x), leaky(c3.y));
        *reinterpret_cast<float4*>(out + r * N_ + tx * 8) = o0;
        *reinterpret_cast<float4*>(out + r * N_ + tx * 8 + 4) = o1;
    }
}

// ---------------- kernel 6: y = leaky(w_dyn @ y1 + b_dyn) ----------------
__global__ void __launch_bounds__(256, 2) k_y2(const float* __restrict__ w_dyn,
                                               const float* __restrict__ b_dyn,
                                               float* __restrict__ out) {
    __shared__ float As[2][8][128], Bs[2][8][128];
    int nt = blockIdx.x, b = blockIdx.y;
    int tid = threadIdx.x, ty = tid >> 4, tx = tid & 15;
    int n0 = nt * 128;
    const float* Bbase = g_y1 + b * C_ * N_ + n0;
    u64 acc[8][4] = {};
    float4 va = lda_g(w_dyn, C_, 0, tid);
    float4 vb = ldb_g(Bbase, N_, tid);
    sta_s(As[0], va, tid);
    stb_s(Bs[0], vb, tid);
    __syncthreads();
    int buf = 0;
    for (int kk = 8; kk < C_; kk += 8) {
        va = lda_g(w_dyn, C_, kk, tid);
        vb = ldb_g(Bbase + kk * N_, N_, tid);
        mm8(As[buf], Bs[buf], acc, ty, tx);
        sta_s(As[buf ^ 1], va, tid);
        stb_s(Bs[buf ^ 1], vb, tid);
        __syncthreads();
        buf ^= 1;
    }
    mm8(As[buf], Bs[buf], acc, ty, tx);
    float* o = out + b * C_ * N_ + n0;
#pragma unroll
    for (int i = 0; i < 8; ++i) {
        int r = ty * 8 + i;
        float bias = b_dyn[r];
        float2 c0 = unpack2(acc[i][0]), c1 = unpack2(acc[i][1]);
        float2 c2 = unpack2(acc[i][2]), c3 = unpack2(acc[i][3]);
        float4 o0 = make_float4(leaky(c0.x + bias), leaky(c0.y + bias),
                                leaky(c1.x + bias), leaky(c1.y + bias));
        float4 o1 = make_float4(leaky(c2.x + bias), leaky(c2.y + bias),
                                leaky(c3.x + bias), leaky(c3.y + bias));
        *reinterpret_cast<float4*>(o + r * N_ + tx * 8) = o0;
        *reinterpret_cast<float4*>(o + r * N_ + tx * 8 + 4) = o1;
    }
}

// ---------------- launch ----------------
extern "C" void kernel_launch(void* const* d_in, const int* in_sizes, int n_in,
                              void* d_out, int out_size) {
    const float* x     = (const float*)d_in[0];  // [8,128,2048]
    const float* w_adj = (const float*)d_in[1];  // [2048,256]
    const float* b_adj = (const float*)d_in[2];  // [2048]
    const float* w_dyn = (const float*)d_in[3];  // [128,128]
    const float* b_dyn = (const float*)d_in[4];  // [128]
    const float* gamma = (const float*)d_in[5];  // [1]
    float* out = (float*)d_out;                  // [8,128,2048]

    k_energy<<<dim3(B_, KSPLIT), 256>>>(x);
    k_softmax<<<256, 128>>>();
    k_xglb<<<dim3(N_ / 128, B_), 256>>>(x, gamma);
    k_adj<<<dim3(N_ / 128, N_ / 128, B_), 256>>>(x, w_adj, b_adj);
    k_y1<<<dim3(N_ / 128, B_), 256>>>(x);
    k_y2<<<dim3(N_ / 128, B_), 256>>>(w_dyn, b_dyn, out);
}

// round 5
// speedup vs baseline: 1.7991x; 1.3902x over previous
#include <cuda_runtime.h>
#include <cuda_bf16.h>
#include <cstdint>
#include <math.h>

// Problem constants
#define B_ 8
#define C_ 128
#define N_ 2048
#define K2C 256
#define KSPLIT 16
#define SLOPE 0.2f

typedef unsigned long long u64;
typedef unsigned int u32;

// ---------------- device scratch (allocation-free) ----------------
__device__ float g_epart[KSPLIT * B_ * C_ * C_];   // partial energy
__device__ float g_att[B_ * C_ * C_];              // attention
__device__ float g_xglb[B_ * C_ * N_];             // gamma*out + x
__device__ float g_adj[(size_t)B_ * N_ * N_];      // 134 MB dynamic adjacency
__device__ float g_y1[B_ * C_ * N_];               // leaky(x @ adj)

// =====================================================================
// mma.sync (HMMA) path — works on base sm_100 (no 'a' features)
// =====================================================================
__device__ __forceinline__ u32 smem_u32(const void* p) {
    u32 a;
    asm("{ .reg .u64 t; cvta.to.shared.u64 t, %1; cvt.u32.u64 %0, t; }"
        : "=r"(a) : "l"(p));
    return a;
}

__device__ __forceinline__ void ldsm4(u32* r, u32 addr) {
    asm volatile("ldmatrix.sync.aligned.m8n8.x4.shared.b16 {%0,%1,%2,%3}, [%4];"
                 : "=r"(r[0]), "=r"(r[1]), "=r"(r[2]), "=r"(r[3]) : "r"(addr));
}
__device__ __forceinline__ void ldsm2(u32* r, u32 addr) {
    asm volatile("ldmatrix.sync.aligned.m8n8.x2.shared.b16 {%0,%1}, [%2];"
                 : "=r"(r[0]), "=r"(r[1]) : "r"(addr));
}
__device__ __forceinline__ void mma_bf16(float* c, const u32* a, const u32* b) {
    asm volatile(
        "mma.sync.aligned.m16n8k16.row.col.f32.bf16.bf16.f32 "
        "{%0,%1,%2,%3}, {%4,%5,%6,%7}, {%8,%9}, {%0,%1,%2,%3};"
        : "+f"(c[0]), "+f"(c[1]), "+f"(c[2]), "+f"(c[3])
        : "r"(a[0]), "r"(a[1]), "r"(a[2]), "r"(a[3]), "r"(b[0]), "r"(b[1]));
}

// SW128 swizzle (rows of 128 bytes = 64 bf16)
#define SWZ(o) ((o) ^ (((o) >> 3) & 0x70))

// smem layout: 4 tiles of 128 rows x 64 bf16 (16 KB each)
#define OFF_AH 0
#define OFF_AL 16384
#define OFF_BH 32768
#define OFF_BL 49152
#define TC_SMEM_SZ 65536

// convert 8 fp32 -> 8 bf16 hi + 8 bf16 lo (packed 16B each)
__device__ __forceinline__ void cvt8(const float f[8], uint4& H, uint4& L) {
    u32 hw[4], lw[4];
#pragma unroll
    for (int j = 0; j < 4; ++j) {
        float f0 = f[2 * j], f1 = f[2 * j + 1];
        __nv_bfloat16 h0 = __float2bfloat16_rn(f0);
        __nv_bfloat16 h1 = __float2bfloat16_rn(f1);
        __nv_bfloat16 l0 = __float2bfloat16_rn(f0 - __bfloat162float(h0));
        __nv_bfloat16 l1 = __float2bfloat16_rn(f1 - __bfloat162float(h1));
        hw[j] = (u32)__bfloat16_as_ushort(h0) | ((u32)__bfloat16_as_ushort(h1) << 16);
        lw[j] = (u32)__bfloat16_as_ushort(l0) | ((u32)__bfloat16_as_ushort(l1) << 16);
    }
    H = make_uint4(hw[0], hw[1], hw[2], hw[3]);
    L = make_uint4(lw[0], lw[1], lw[2], lw[3]);
}

// Stage A tile [128 rows x 64 k] from row-major(k contiguous) source, hi/lo split
__device__ __forceinline__ void stage_A(char* sm, const float* __restrict__ A,
                                        int lda, int tid) {
    int row = tid & 127, cg = tid >> 7;
#pragma unroll
    for (int i = 0; i < 4; ++i) {
        int col = cg * 8 + i * 16;
        const float* p = A + (size_t)row * lda + col;
        float4 v0 = *reinterpret_cast<const float4*>(p);
        float4 v1 = *reinterpret_cast<const float4*>(p + 4);
        float f[8] = {v0.x, v0.y, v0.z, v0.w, v1.x, v1.y, v1.z, v1.w};
        uint4 H, L;
        cvt8(f, H, L);
        int so = SWZ(row * 128 + col * 2);
        *reinterpret_cast<uint4*>(sm + OFF_AH + so) = H;
        *reinterpret_cast<uint4*>(sm + OFF_AL + so) = L;
    }
}

// Stage B transposed: smem[n][k] (128 n x 64 k) from S[k][n] (n contiguous)
__device__ __forceinline__ void stage_BT(char* sm, const float* __restrict__ S,
                                         int lds, int tid) {
    int n = tid & 127, kg = tid >> 7;
#pragma unroll
    for (int j = 0; j < 4; ++j) {
        int kb = kg * 32 + j * 8;
        float f[8];
#pragma unroll
        for (int u = 0; u < 8; ++u) f[u] = S[(size_t)(kb + u) * lds + n];
        uint4 H, L;
        cvt8(f, H, L);
        int so = SWZ(n * 128 + kb * 2);
        *reinterpret_cast<uint4*>(sm + OFF_BH + so) = H;
        *reinterpret_cast<uint4*>(sm + OFF_BL + so) = L;
    }
}

__device__ __forceinline__ float leaky(float v) { return v > 0.0f ? v : SLOPE * v; }
__device__ __forceinline__ float sigm(float v) { return 1.0f / (1.0f + __expf(-v)); }

// One K-chunk (64 k) of bf16x3 MMAs. Warp tile 32(m) x 64(n).
__device__ __forceinline__ void compute_chunk(u32 sb, int wm, int wn, int lane,
                                              float acc[2][8][4]) {
    int mrow = lane & 15, msel = lane >> 4;
    int brow = lane & 7, bsel = (lane >> 3) & 1;
#pragma unroll
    for (int s = 0; s < 4; ++s) {
        int k0 = s * 16;
        u32 ah[2][4], al[2][4];
#pragma unroll
        for (int mf = 0; mf < 2; ++mf) {
            int m = wm + mf * 16 + mrow;
            int k = k0 + msel * 8;
            u32 off = (u32)SWZ(m * 128 + k * 2);
            ldsm4(ah[mf], sb + OFF_AH + off);
            ldsm4(al[mf], sb + OFF_AL + off);
        }
#pragma unroll
        for (int ng = 0; ng < 2; ++ng) {
            u32 bh[4][2], bl[4][2];
#pragma unroll
            for (int nf = 0; nf < 4; ++nf) {
                int n = wn + (ng * 4 + nf) * 8 + brow;
                int k = k0 + bsel * 8;
                u32 off = (u32)SWZ(n * 128 + k * 2);
                ldsm2(bh[nf], sb + OFF_BH + off);
                ldsm2(bl[nf], sb + OFF_BL + off);
            }
#pragma unroll
            for (int mf = 0; mf < 2; ++mf)
#pragma unroll
                for (int nf = 0; nf < 4; ++nf) {
                    float* c = acc[mf][ng * 4 + nf];
                    mma_bf16(c, ah[mf], bh[nf]);
                    mma_bf16(c, ah[mf], bl[nf]);
                    mma_bf16(c, al[mf], bh[nf]);
                }
        }
    }
}

// ---------------- k_adj: adj = sigmoid(w_adj @ [x_glb; x] + b_adj) ----------
__global__ void __launch_bounds__(256, 2) k_adj_tc(const float* __restrict__ x,
                                                   const float* __restrict__ w_adj,
                                                   const float* __restrict__ b_adj) {
    extern __shared__ __align__(1024) char sm[];
    u32 sb = smem_u32(sm);
    int tid = threadIdx.x, wid = tid >> 5, lane = tid & 31;
    int n0 = blockIdx.x * 128, m0 = blockIdx.y * 128, b = blockIdx.z;
    int wm = (wid >> 1) * 32, wn = (wid & 1) * 64;

    float acc[2][8][4] = {};
    for (int kc = 0; kc < 4; ++kc) {
        int kb = kc * 64;
        stage_A(sm, w_adj + (size_t)m0 * K2C + kb, K2C, tid);
        const float* bsrc = (kc < 2)
            ? (g_xglb + (size_t)b * C_ * N_ + (size_t)kb * N_ + n0)
            : (x + (size_t)b * C_ * N_ + (size_t)(kb - 128) * N_ + n0);
        stage_BT(sm, bsrc, N_, tid);
        __syncthreads();
        compute_chunk(sb, wm, wn, lane, acc);
        __syncthreads();
    }

    // epilogue: sigmoid(acc + bias)
    float* obase = g_adj + (size_t)b * N_ * N_;
#pragma unroll
    for (int mf = 0; mf < 2; ++mf) {
        int r = wm + mf * 16 + (lane >> 2);
        float bias0 = b_adj[m0 + r];
        float bias1 = b_adj[m0 + r + 8];
#pragma unroll
        for (int nf = 0; nf < 8; ++nf) {
            int c = wn + nf * 8 + (lane & 3) * 2;
            float* p0 = obase + (size_t)(m0 + r) * N_ + n0 + c;
            float* p1 = obase + (size_t)(m0 + r + 8) * N_ + n0 + c;
            const float* a = acc[mf][nf];
            *reinterpret_cast<float2*>(p0) =
                make_float2(sigm(a[0] + bias0), sigm(a[1] + bias0));
            *reinterpret_cast<float2*>(p1) =
                make_float2(sigm(a[2] + bias1), sigm(a[3] + bias1));
        }
    }
}

// ---------------- k_y1: y1 = leaky(x @ adj) ----------------------------------
__global__ void __launch_bounds__(256, 2) k_y1_tc(const float* __restrict__ x) {
    extern __shared__ __align__(1024) char sm[];
    u32 sb = smem_u32(sm);
    int tid = threadIdx.x, wid = tid >> 5, lane = tid & 31;
    int n0 = blockIdx.x * 128, b = blockIdx.y;
    int wm = (wid >> 1) * 32, wn = (wid & 1) * 64;

    const float* A = x + (size_t)b * C_ * N_;               // [128, 2048] k contig
    const float* Bb = g_adj + (size_t)b * N_ * N_ + n0;     // [2048 k, n]

    float acc[2][8][4] = {};
    for (int kc = 0; kc < 32; ++kc) {
        int kb = kc * 64;
        stage_A(sm, A + kb, N_, tid);
        stage_BT(sm, Bb + (size_t)kb * N_, N_, tid);
        __syncthreads();
        compute_chunk(sb, wm, wn, lane, acc);
        __syncthreads();
    }

    // epilogue: leaky
    float* obase = g_y1 + (size_t)b * C_ * N_;
#pragma unroll
    for (int mf = 0; mf < 2; ++mf) {
        int r = wm + mf * 16 + (lane >> 2);
#pragma unroll
        for (int nf = 0; nf < 8; ++nf) {
            int c = wn + nf * 8 + (lane & 3) * 2;
            float* p0 = obase + (size_t)r * N_ + n0 + c;
            float* p1 = obase + (size_t)(r + 8) * N_ + n0 + c;
            const float* a = acc[mf][nf];
            *reinterpret_cast<float2*>(p0) = make_float2(leaky(a[0]), leaky(a[1]));
            *reinterpret_cast<float2*>(p1) = make_float2(leaky(a[2]), leaky(a[3]));
        }
    }
}

// =====================================================================
// SIMT kernels (round 2, unchanged): energy, softmax, xglb, y2
// =====================================================================
__device__ __forceinline__ u64 pack2(float x, float y) {
    u64 r;
    asm("mov.b64 %0, {%1, %2};" : "=l"(r) : "f"(x), "f"(y));
    return r;
}
__device__ __forceinline__ float2 unpack2(u64 v) {
    float2 r;
    asm("mov.b64 {%0, %1}, %2;" : "=f"(r.x), "=f"(r.y) : "l"(v));
    return r;
}
__device__ __forceinline__ void ffma2(u64& d, u64 a, u64 b) {
    asm("fma.rn.f32x2 %0, %1, %2, %0;" : "+l"(d) : "l"(a), "l"(b));
}
__device__ __forceinline__ float4 lda_g(const float* __restrict__ A, int lda,
                                        int kk, int tid) {
    int m = tid & 127, j = tid >> 7;
    return *reinterpret_cast<const float4*>(A + m * lda + kk + j * 4);
}
__device__ __forceinline__ void sta_s(float As[8][128], float4 v, int tid) {
    int m = tid & 127, j = tid >> 7;
    As[j * 4 + 0][m] = v.x;
    As[j * 4 + 1][m] = v.y;
    As[j * 4 + 2][m] = v.z;
    As[j * 4 + 3][m] = v.w;
}
__device__ __forceinline__ float4 ldb_g(const float* __restrict__ Brow, int ldb,
                                        int tid) {
    int t = tid >> 5, nc = (tid & 31) << 2;
    return *reinterpret_cast<const float4*>(Brow + t * ldb + nc);
}
__device__ __forceinline__ void stb_s(float Bs[8][128], float4 v, int tid) {
    int t = tid >> 5, nc = (tid & 31) << 2;
    *reinterpret_cast<float4*>(&Bs[t][nc]) = v;
}
__device__ __forceinline__ void mm8(const float As[8][128], const float Bs[8][128],
                                    u64 acc[8][4], int ty, int tx) {
#pragma unroll
    for (int t = 0; t < 8; ++t) {
        float4 a0 = *reinterpret_cast<const float4*>(&As[t][ty * 8]);
        float4 a1 = *reinterpret_cast<const float4*>(&As[t][ty * 8 + 4]);
        const ulonglong2* bp = reinterpret_cast<const ulonglong2*>(&Bs[t][tx * 8]);
        ulonglong2 bA = bp[0], bB = bp[1];
        u64 b[4] = {bA.x, bA.y, bB.x, bB.y};
        float a[8] = {a0.x, a0.y, a0.z, a0.w, a1.x, a1.y, a1.z, a1.w};
#pragma unroll
        for (int i = 0; i < 8; ++i) {
            u64 ai = pack2(a[i], a[i]);
#pragma unroll
            for (int j = 0; j < 4; ++j) ffma2(acc[i][j], ai, b[j]);
        }
    }
}

__global__ void __launch_bounds__(256, 2) k_energy(const float* __restrict__ x) {
    __shared__ float S[2][8][128];
    int b = blockIdx.x, ks = blockIdx.y;
    int tid = threadIdx.x, ty = tid >> 4, tx = tid & 15;
    const float* A = x + b * C_ * N_ + ks * (N_ / KSPLIT);
    u64 acc[8][4] = {};
    float4 v = lda_g(A, N_, 0, tid);
    sta_s(S[0], v, tid);
    __syncthreads();
    int buf = 0;
    for (int kk = 8; kk < N_ / KSPLIT; kk += 8) {
        v = lda_g(A, N_, kk, tid);
        mm8(S[buf], S[buf], acc, ty, tx);
        sta_s(S[buf ^ 1], v, tid);
        __syncthreads();
        buf ^= 1;
    }
    mm8(S[buf], S[buf], acc, ty, tx);
    float* out = g_epart + ((ks * B_ + b) * C_) * C_;
#pragma unroll
    for (int i = 0; i < 8; ++i) {
        int r = ty * 8 + i;
        float2 c0 = unpack2(acc[i][0]), c1 = unpack2(acc[i][1]);
        float2 c2 = unpack2(acc[i][2]), c3 = unpack2(acc[i][3]);
        *reinterpret_cast<float4*>(out + r * C_ + tx * 8) =
            make_float4(c0.x, c0.y, c1.x, c1.y);
        *reinterpret_cast<float4*>(out + r * C_ + tx * 8 + 4) =
            make_float4(c2.x, c2.y, c3.x, c3.y);
    }
}

__global__ void __launch_bounds__(128) k_softmax() {
    int warp = threadIdx.x >> 5, lane = threadIdx.x & 31;
    int row = blockIdx.x * 4 + warp;
    int b = row >> 7, c = row & 127;
    float e[4];
#pragma unroll
    for (int q = 0; q < 4; ++q) {
        int d = lane + q * 32;
        float s = 0.0f;
#pragma unroll
        for (int p = 0; p < KSPLIT; ++p)
            s += g_epart[((p * B_ + b) * C_ + c) * C_ + d];
        e[q] = -s;
    }
    float m = fmaxf(fmaxf(e[0], e[1]), fmaxf(e[2], e[3]));
#pragma unroll
    for (int off = 16; off > 0; off >>= 1)
        m = fmaxf(m, __shfl_xor_sync(0xffffffffu, m, off));
    float p4[4], s = 0.0f;
#pragma unroll
    for (int q = 0; q < 4; ++q) {
        p4[q] = __expf(e[q] - m);
        s += p4[q];
    }
#pragma unroll
    for (int off = 16; off > 0; off >>= 1)
        s += __shfl_xor_sync(0xffffffffu, s, off);
    float inv = 1.0f / s;
#pragma unroll
    for (int q = 0; q < 4; ++q)
        g_att[(b * C_ + c) * C_ + lane + q * 32] = p4[q] * inv;
}

__global__ void __launch_bounds__(256, 2) k_xglb(const float* __restrict__ x,
                                                 const float* __restrict__ gamma) {
    __shared__ float As[2][8][128], Bs[2][8][128];
    int nt = blockIdx.x, b = blockIdx.y;
    int tid = threadIdx.x, ty = tid >> 4, tx = tid & 15;
    int n0 = nt * 128;
    const float* A = g_att + b * C_ * C_;
    const float* Bbase = x + b * C_ * N_ + n0;
    u64 acc[8][4] = {};
    float4 va = lda_g(A, C_, 0, tid);
    float4 vb = ldb_g(Bbase, N_, tid);
    sta_s(As[0], va, tid);
    stb_s(Bs[0], vb, tid);
    __syncthreads();
    int buf = 0;
    for (int kk = 8; kk < C_; kk += 8) {
        va = lda_g(A, C_, kk, tid);
        vb = ldb_g(Bbase + kk * N_, N_, tid);
        mm8(As[buf], Bs[buf], acc, ty, tx);
        sta_s(As[buf ^ 1], va, tid);
        stb_s(Bs[buf ^ 1], vb, tid);
        __syncthreads();
        buf ^= 1;
    }
    mm8(As[buf], Bs[buf], acc, ty, tx);
    float gm = *gamma;
    float* out = g_xglb + b * C_ * N_ + n0;
    const float* xr = x + b * C_ * N_ + n0;
#pragma unroll
    for (int i = 0; i < 8; ++i) {
        int r = ty * 8 + i;
        float2 c0 = unpack2(acc[i][0]), c1 = unpack2(acc[i][1]);
        float2 c2 = unpack2(acc[i][2]), c3 = unpack2(acc[i][3]);
        float4 xv0 = *reinterpret_cast<const float4*>(xr + r * N_ + tx * 8);
        float4 xv1 = *reinterpret_cast<const float4*>(xr + r * N_ + tx * 8 + 4);
        float4 o0 = make_float4(fmaf(gm, c0.x, xv0.x), fmaf(gm, c0.y, xv0.y),
                                fmaf(gm, c1.x, xv0.z), fmaf(gm, c1.y, xv0.w));
        float4 o1 = make_float4(fmaf(gm, c2.x, xv1.x), fmaf(gm, c2.y, xv1.y),
                                fmaf(gm, c3.x, xv1.z), fmaf(gm, c3.y, xv1.w));
        *reinterpret_cast<float4*>(out + r * N_ + tx * 8) = o0;
        *reinterpret_cast<float4*>(out + r * N_ + tx * 8 + 4) = o1;
    }
}

__global__ void __launch_bounds__(256, 2) k_y2(const float* __restrict__ w_dyn,
                                               const float* __restrict__ b_dyn,
                                               float* __restrict__ out) {
    __shared__ float As[2][8][128], Bs[2][8][128];
    int nt = blockIdx.x, b = blockIdx.y;
    int tid = threadIdx.x, ty = tid >> 4, tx = tid & 15;
    int n0 = nt * 128;
    const float* Bbase = g_y1 + b * C_ * N_ + n0;
    u64 acc[8][4] = {};
    float4 va = lda_g(w_dyn, C_, 0, tid);
    float4 vb = ldb_g(Bbase, N_, tid);
    sta_s(As[0], va, tid);
    stb_s(Bs[0], vb, tid);
    __syncthreads();
    int buf = 0;
    for (int kk = 8; kk < C_; kk += 8) {
        va = lda_g(w_dyn, C_, kk, tid);
        vb = ldb_g(Bbase + kk * N_, N_, tid);
        mm8(As[buf], Bs[buf], acc, ty, tx);
        sta_s(As[buf ^ 1], va, tid);
        stb_s(Bs[buf ^ 1], vb, tid);
        __syncthreads();
        buf ^= 1;
    }
    mm8(As[buf], Bs[buf], acc, ty, tx);
    float* o = out + b * C_ * N_ + n0;
#pragma unroll
    for (int i = 0; i < 8; ++i) {
        int r = ty * 8 + i;
        float bias = b_dyn[r];
        float2 c0 = unpack2(acc[i][0]), c1 = unpack2(acc[i][1]);
        float2 c2 = unpack2(acc[i][2]), c3 = unpack2(acc[i][3]);
        float4 o0 = make_float4(leaky(c0.x + bias), leaky(c0.y + bias),
                                leaky(c1.x + bias), leaky(c1.y + bias));
        float4 o1 = make_float4(leaky(c2.x + bias), leaky(c2.y + bias),
                                leaky(c3.x + bias), leaky(c3.y + bias));
        *reinterpret_cast<float4*>(o + r * N_ + tx * 8) = o0;
        *reinterpret_cast<float4*>(o + r * N_ + tx * 8 + 4) = o1;
    }
}

// ---------------- launch ----------------
extern "C" void kernel_launch(void* const* d_in, const int* in_sizes, int n_in,
                              void* d_out, int out_size) {
    const float* x     = (const float*)d_in[0];  // [8,128,2048]
    const float* w_adj = (const float*)d_in[1];  // [2048,256]
    const float* b_adj = (const float*)d_in[2];  // [2048]
    const float* w_dyn = (const float*)d_in[3];  // [128,128]
    const float* b_dyn = (const float*)d_in[4];  // [128]
    const float* gamma = (const float*)d_in[5];  // [1]
    float* out = (float*)d_out;                  // [8,128,2048]

    cudaFuncSetAttribute(k_adj_tc, cudaFuncAttributeMaxDynamicSharedMemorySize,
                         TC_SMEM_SZ);
    cudaFuncSetAttribute(k_y1_tc, cudaFuncAttributeMaxDynamicSharedMemorySize,
                         TC_SMEM_SZ);

    k_energy<<<dim3(B_, KSPLIT), 256>>>(x);
    k_softmax<<<256, 128>>>();
    k_xglb<<<dim3(N_ / 128, B_), 256>>>(x, gamma);
    k_adj_tc<<<dim3(N_ / 128, N_ / 128, B_), 256, TC_SMEM_SZ>>>(x, w_adj, b_adj);
    k_y1_tc<<<dim3(N_ / 128, B_), 256, TC_SMEM_SZ>>>(x);
    k_y2<<<dim3(N_ / 128, B_), 256>>>(w_dyn, b_dyn, out);
}

// round 6
// speedup vs baseline: 2.2193x; 1.2336x over previous
#include <cuda_runtime.h>
#include <cuda_bf16.h>
#include <cstdint>
#include <math.h>

#define B_ 8
#define C_ 128
#define N_ 2048
#define K2C 256
#define KSPLIT 16
#define SLOPE 0.2f

typedef unsigned int u32;
typedef unsigned long long u64;
typedef __nv_bfloat16 bf16;

// ---------------- device scratch (allocation-free) ----------------
__device__ float g_epart[KSPLIT * B_ * C_ * C_];                    // energy partials
__device__ bf16 g_xcH[B_ * K2C * N_], g_xcL[B_ * K2C * N_];         // xc = [x_glb; x]
__device__ bf16 g_wadjH[N_ * K2C], g_wadjL[N_ * K2C];
__device__ bf16 g_wdynH[C_ * C_], g_wdynL[C_ * C_];
__device__ bf16 g_attH[B_ * C_ * C_], g_attL[B_ * C_ * C_];
__device__ bf16 g_adjH[(size_t)B_ * N_ * N_], g_adjL[(size_t)B_ * N_ * N_];
__device__ bf16 g_y1H[B_ * C_ * N_], g_y1L[B_ * C_ * N_];

// ---------------- primitives ----------------
__device__ __forceinline__ u32 smem_u32(const void* p) {
    u32 a;
    asm("{ .reg .u64 t; cvta.to.shared.u64 t, %1; cvt.u32.u64 %0, t; }"
        : "=r"(a) : "l"(p));
    return a;
}
__device__ __forceinline__ void ldsm4(u32* r, u32 addr) {
    asm volatile("ldmatrix.sync.aligned.m8n8.x4.shared.b16 {%0,%1,%2,%3}, [%4];"
                 : "=r"(r[0]), "=r"(r[1]), "=r"(r[2]), "=r"(r[3]) : "r"(addr));
}
__device__ __forceinline__ void ldsm4t(u32* r, u32 addr) {
    asm volatile("ldmatrix.sync.aligned.m8n8.x4.trans.shared.b16 {%0,%1,%2,%3}, [%4];"
                 : "=r"(r[0]), "=r"(r[1]), "=r"(r[2]), "=r"(r[3]) : "r"(addr));
}
__device__ __forceinline__ void mma_bf16(float* c, const u32* a, const u32* b) {
    asm volatile(
        "mma.sync.aligned.m16n8k16.row.col.f32.bf16.bf16.f32 "
        "{%0,%1,%2,%3}, {%4,%5,%6,%7}, {%8,%9}, {%0,%1,%2,%3};"
        : "+f"(c[0]), "+f"(c[1]), "+f"(c[2]), "+f"(c[3])
        : "r"(a[0]), "r"(a[1]), "r"(a[2]), "r"(a[3]), "r"(b[0]), "r"(b[1]));
}
__device__ __forceinline__ void cpa16(u32 dst, const void* src) {
    asm volatile("cp.async.cg.shared.global [%0], [%1], 16;" :: "r"(dst), "l"(src));
}
#define CP_COMMIT() asm volatile("cp.async.commit_group;" ::: "memory")
#define CP_WAIT1() asm volatile("cp.async.wait_group 1;" ::: "memory")
#define CP_WAIT0() asm volatile("cp.async.wait_group 0;" ::: "memory")

#define SWZ(o) ((o) ^ (((o) >> 3) & 0x70))

// smem: 2 buffers x (AH, AL [m][k] 128x64 16KB; BH, BL [k][n] 64x128 16KB)
#define SM_AH(b) ((b) * 65536 + 0)
#define SM_AL(b) ((b) * 65536 + 16384)
#define SM_BH(b) ((b) * 65536 + 32768)
#define SM_BL(b) ((b) * 65536 + 49152)
#define SMEM_SZ 131072

__device__ __forceinline__ void split1(float v, bf16& h, bf16& l) {
    h = __float2bfloat16_rn(v);
    l = __float2bfloat16_rn(v - __bfloat162float(h));
}
__device__ __forceinline__ u32 packbf2(bf16 a, bf16 b) {
    return (u32)__bfloat16_as_ushort(a) | ((u32)__bfloat16_as_ushort(b) << 16);
}
__device__ __forceinline__ float leaky(float v) { return v > 0.0f ? v : SLOPE * v; }
__device__ __forceinline__ float sigm(float v) { return 1.0f / (1.0f + __expf(-v)); }

// Stage A-type tile (128 rows x 64 k) from bf16 row-major src, SW128 swizzle.
__device__ __forceinline__ void stA(u32 sbase, const bf16* __restrict__ src,
                                    int lda, int tid) {
    int row = tid & 127, g = tid >> 7;
    const bf16* p = src + (size_t)row * lda + g * 32;
#pragma unroll
    for (int i = 0; i < 4; ++i) {
        int ch = g * 4 + i;
        cpa16(sbase + (u32)SWZ(row * 128 + ch * 16), p + i * 8);
    }
}
// Stage B-type tile (64 k rows x 128 n) from bf16 [k][n] src, XOR chunk swizzle.
__device__ __forceinline__ void stB(u32 sbase, const bf16* __restrict__ src,
                                    int ldb, int tid) {
    int kr = tid >> 2, q = tid & 3;
    const bf16* p = src + (size_t)kr * ldb + q * 32;
#pragma unroll
    for (int i = 0; i < 4; ++i) {
        int ch = q * 4 + i;
        cpa16(sbase + (u32)(kr * 256 + ((ch ^ (kr & 15)) & 15) * 16), p + i * 8);
    }
}

// One 64-k chunk of split-precision MMAs. Warp tile 32(m) x 64(n).
// BTRANS: B frags from [k][n] tile via ldmatrix.trans. Else B frags from
// the A-type tile (non-trans, rows = n) — used by the symmetric energy GEMM.
// FOUR: include the AlBl pass (bf16x4) for higher precision.
template <bool BTRANS, bool FOUR>
__device__ __forceinline__ void chunk_mma(u32 sAH, u32 sAL, u32 sBH, u32 sBL,
                                          int wm, int wn, int lane,
                                          float acc[2][8][4]) {
#pragma unroll
    for (int s = 0; s < 4; ++s) {
        int k0 = s * 16;
        u32 ah[2][4], al[2][4];
        {
            int am = lane & 15, ak = k0 + (lane >> 4) * 8;
            u32 o0 = (u32)SWZ((wm + am) * 128 + ak * 2);
            u32 o1 = (u32)SWZ((wm + 16 + am) * 128 + ak * 2);
            ldsm4(ah[0], sAH + o0);
            ldsm4(ah[1], sAH + o1);
            ldsm4(al[0], sAL + o0);
            ldsm4(al[1], sAL + o1);
        }
#pragma unroll
        for (int g = 0; g < 4; ++g) {
            u32 bh[4], bl[4];
            if (BTRANS) {
                int t = lane >> 3, r = lane & 7;
                int k = k0 + (t & 1) * 8 + r;
                int nc = ((wn + g * 16) >> 3) + (t >> 1);
                u32 boff = (u32)(k * 256 + ((nc ^ (k & 15)) & 15) * 16);
                ldsm4t(bh, sBH + boff);
                ldsm4t(bl, sBL + boff);
            } else {
                int t = lane >> 3, r = lane & 7;
                int n = wn + g * 16 + (t >> 1) * 8 + r;
                int k = k0 + (t & 1) * 8;
                u32 boff = (u32)SWZ(n * 128 + k * 2);
                ldsm4(bh, sBH + boff);
                ldsm4(bl, sBL + boff);
            }
#pragma unroll
            for (int mf = 0; mf < 2; ++mf)
#pragma unroll
                for (int nf = 0; nf < 2; ++nf) {
                    float* c = acc[mf][g * 2 + nf];
                    mma_bf16(c, ah[mf], bh + nf * 2);
                    mma_bf16(c, ah[mf], bl + nf * 2);
                    mma_bf16(c, al[mf], bh + nf * 2);
                    if (FOUR) mma_bf16(c, al[mf], bl + nf * 2);
                }
        }
    }
}

// Double-buffered mainloop. A advances +64 elems/chunk, B +64 rows/chunk.
template <bool BTRANS, bool FOUR>
__device__ __forceinline__ void gemm_main(u32 sb, const bf16* aH, const bf16* aL,
                                          int lda, const bf16* bH, const bf16* bL,
                                          int ldb, int nc_total, int tid, int wm,
                                          int wn, int lane, float acc[2][8][4]) {
    stA(sb + SM_AH(0), aH, lda, tid);
    stA(sb + SM_AL(0), aL, lda, tid);
    if (BTRANS) {
        stB(sb + SM_BH(0), bH, ldb, tid);
        stB(sb + SM_BL(0), bL, ldb, tid);
    }
    CP_COMMIT();
#pragma unroll 1
    for (int kc = 0; kc < nc_total; ++kc) {
        if (kc + 1 < nc_total) {
            int nb = (kc + 1) & 1;
            stA(sb + SM_AH(nb), aH + (size_t)(kc + 1) * 64, lda, tid);
            stA(sb + SM_AL(nb), aL + (size_t)(kc + 1) * 64, lda, tid);
            if (BTRANS) {
                stB(sb + SM_BH(nb), bH + (size_t)(kc + 1) * 64 * ldb, ldb, tid);
                stB(sb + SM_BL(nb), bL + (size_t)(kc + 1) * 64 * ldb, ldb, tid);
            }
            CP_COMMIT();
            CP_WAIT1();
        } else {
            CP_WAIT0();
        }
        __syncthreads();
        int cb = kc & 1;
        u32 sbh = BTRANS ? sb + SM_BH(cb) : sb + SM_AH(cb);
        u32 sbl = BTRANS ? sb + SM_BL(cb) : sb + SM_AL(cb);
        chunk_mma<BTRANS, FOUR>(sb + SM_AH(cb), sb + SM_AL(cb), sbh, sbl, wm, wn,
                                lane, acc);
        __syncthreads();
    }
}

// ---------------- pre-pass: convert weights + x to bf16 hi/lo ----------------
__global__ void k_cvt(const float* __restrict__ w_adj,
                      const float* __restrict__ w_dyn,
                      const float* __restrict__ x) {
    int i0 = blockIdx.x * blockDim.x + threadIdx.x;
    int st = gridDim.x * blockDim.x;
    bf16 h, l;
    for (int i = i0; i < N_ * K2C; i += st) {
        split1(w_adj[i], h, l);
        g_wadjH[i] = h;
        g_wadjL[i] = l;
    }
    for (int i = i0; i < C_ * C_; i += st) {
        split1(w_dyn[i], h, l);
        g_wdynH[i] = h;
        g_wdynL[i] = l;
    }
    for (int i = i0; i < B_ * C_ * N_; i += st) {
        int b = i / (C_ * N_);
        int rem = i - b * C_ * N_;
        size_t dst = (size_t)b * K2C * N_ + 128 * N_ + rem;  // xc rows 128..255 = x
        split1(x[i], h, l);
        g_xcH[dst] = h;
        g_xcL[dst] = l;
    }
}

// ---------------- energy partials: E_part[ks][b] = x_ks @ x_ks^T (bf16x4) ----
__global__ void __launch_bounds__(256) k_energy_tc() {
    extern __shared__ __align__(1024) char sm[];
    u32 sb = smem_u32(sm);
    int tid = threadIdx.x, wid = tid >> 5, lane = tid & 31;
    int wm = (wid >> 1) * 32, wn = (wid & 1) * 64;
    int ks = blockIdx.x, b = blockIdx.y;
    const bf16* aH = g_xcH + ((size_t)b * K2C + 128) * N_ + ks * 128;
    const bf16* aL = g_xcL + ((size_t)b * K2C + 128) * N_ + ks * 128;
    float acc[2][8][4] = {};
    gemm_main<false, true>(sb, aH, aL, N_, aH, aL, 0, 2, tid, wm, wn, lane, acc);
    float* out = g_epart + ((size_t)(ks * B_ + b) * C_) * C_;
#pragma unroll
    for (int mf = 0; mf < 2; ++mf) {
        int r = wm + mf * 16 + (lane >> 2);
#pragma unroll
        for (int nf = 0; nf < 8; ++nf) {
            int c = wn + nf * 8 + (lane & 3) * 2;
            const float* a = acc[mf][nf];
            *reinterpret_cast<float2*>(out + r * C_ + c) = make_float2(a[0], a[1]);
            *reinterpret_cast<float2*>(out + (r + 8) * C_ + c) = make_float2(a[2], a[3]);
        }
    }
}

// ---------------- softmax(-energy) -> att bf16 hi/lo -------------------------
__global__ void __launch_bounds__(128) k_softmax() {
    int warp = threadIdx.x >> 5, lane = threadIdx.x & 31;
    int row = blockIdx.x * 4 + warp;
    int b = row >> 7, c = row & 127;
    float e[4];
#pragma unroll
    for (int q = 0; q < 4; ++q) {
        int d = lane + q * 32;
        float s = 0.0f;
#pragma unroll
        for (int p = 0; p < KSPLIT; ++p)
            s += g_epart[((p * B_ + b) * C_ + c) * C_ + d];
        e[q] = -s;
    }
    float m = fmaxf(fmaxf(e[0], e[1]), fmaxf(e[2], e[3]));
#pragma unroll
    for (int off = 16; off > 0; off >>= 1)
        m = fmaxf(m, __shfl_xor_sync(0xffffffffu, m, off));
    float p4[4], s = 0.0f;
#pragma unroll
    for (int q = 0; q < 4; ++q) {
        p4[q] = __expf(e[q] - m);
        s += p4[q];
    }
#pragma unroll
    for (int off = 16; off > 0; off >>= 1)
        s += __shfl_xor_sync(0xffffffffu, s, off);
    float inv = 1.0f / s;
#pragma unroll
    for (int q = 0; q < 4; ++q) {
        bf16 h, l;
        split1(p4[q] * inv, h, l);
        g_attH[(b * C_ + c) * C_ + lane + q * 32] = h;
        g_attL[(b * C_ + c) * C_ + lane + q * 32] = l;
    }
}

// ---------------- x_glb = gamma*(att @ x) + x -> xc rows 0..127 --------------
__global__ void __launch_bounds__(256) k_xglb_tc(const float* __restrict__ x,
                                                 const float* __restrict__ gamma) {
    extern __shared__ __align__(1024) char sm[];
    u32 sb = smem_u32(sm);
    int tid = threadIdx.x, wid = tid >> 5, lane = tid & 31;
    int wm = (wid >> 1) * 32, wn = (wid & 1) * 64;
    int n0 = blockIdx.x * 128, b = blockIdx.y;
    const bf16* aH = g_attH + (size_t)b * C_ * C_;
    const bf16* aL = g_attL + (size_t)b * C_ * C_;
    const bf16* bH = g_xcH + ((size_t)b * K2C + 128) * N_ + n0;
    const bf16* bL = g_xcL + ((size_t)b * K2C + 128) * N_ + n0;
    float acc[2][8][4] = {};
    gemm_main<true, false>(sb, aH, aL, C_, bH, bL, N_, 2, tid, wm, wn, lane, acc);
    float gm = *gamma;
    const float* xb = x + (size_t)b * C_ * N_;
    bf16* oH = g_xcH + (size_t)b * K2C * N_;
    bf16* oL = g_xcL + (size_t)b * K2C * N_;
#pragma unroll
    for (int mf = 0; mf < 2; ++mf) {
        int r = wm + mf * 16 + (lane >> 2);
#pragma unroll
        for (int nf = 0; nf < 8; ++nf) {
            int c = wn + nf * 8 + (lane & 3) * 2;
            const float* a = acc[mf][nf];
#pragma unroll
            for (int hrow = 0; hrow < 2; ++hrow) {
                int rr = r + hrow * 8;
                float v0 = fmaf(gm, a[hrow * 2 + 0], xb[(size_t)rr * N_ + n0 + c]);
                float v1 = fmaf(gm, a[hrow * 2 + 1], xb[(size_t)rr * N_ + n0 + c + 1]);
                bf16 h0, l0, h1, l1;
                split1(v0, h0, l0);
                split1(v1, h1, l1);
                *reinterpret_cast<u32*>(oH + (size_t)rr * N_ + n0 + c) = packbf2(h0, h1);
                *reinterpret_cast<u32*>(oL + (size_t)rr * N_ + n0 + c) = packbf2(l0, l1);
            }
        }
    }
}

// ---------------- adj = sigmoid(w_adj @ xc + b_adj) -> bf16 hi/lo ------------
__global__ void __launch_bounds__(256) k_adj_tc(const float* __restrict__ b_adj) {
    extern __shared__ __align__(1024) char sm[];
    u32 sb = smem_u32(sm);
    int tid = threadIdx.x, wid = tid >> 5, lane = tid & 31;
    int wm = (wid >> 1) * 32, wn = (wid & 1) * 64;
    int n0 = blockIdx.x * 128, m0 = blockIdx.y * 128, b = blockIdx.z;
    const bf16* aH = g_wadjH + (size_t)m0 * K2C;
    const bf16* aL = g_wadjL + (size_t)m0 * K2C;
    const bf16* bH = g_xcH + (size_t)b * K2C * N_ + n0;
    const bf16* bL = g_xcL + (size_t)b * K2C * N_ + n0;
    float acc[2][8][4] = {};
    gemm_main<true, false>(sb, aH, aL, K2C, bH, bL, N_, 4, tid, wm, wn, lane, acc);
    bf16* oH = g_adjH + (size_t)b * N_ * N_;
    bf16* oL = g_adjL + (size_t)b * N_ * N_;
#pragma unroll
    for (int mf = 0; mf < 2; ++mf) {
        int r = wm + mf * 16 + (lane >> 2);
#pragma unroll
        for (int nf = 0; nf < 8; ++nf) {
            int c = wn + nf * 8 + (lane & 3) * 2;
            const float* a = acc[mf][nf];
#pragma unroll
            for (int hrow = 0; hrow < 2; ++hrow) {
                int rr = r + hrow * 8;
                float bias = b_adj[m0 + rr];
                float v0 = sigm(a[hrow * 2 + 0] + bias);
                float v1 = sigm(a[hrow * 2 + 1] + bias);
                bf16 h0, l0, h1, l1;
                split1(v0, h0, l0);
                split1(v1, h1, l1);
                size_t off = (size_t)(m0 + rr) * N_ + n0 + c;
                *reinterpret_cast<u32*>(oH + off) = packbf2(h0, h1);
                *reinterpret_cast<u32*>(oL + off) = packbf2(l0, l1);
            }
        }
    }
}

// ---------------- y1 = leaky(x @ adj) -> bf16 hi/lo ---------------------------
__global__ void __launch_bounds__(256) k_y1_tc() {
    extern __shared__ __align__(1024) char sm[];
    u32 sb = smem_u32(sm);
    int tid = threadIdx.x, wid = tid >> 5, lane = tid & 31;
    int wm = (wid >> 1) * 32, wn = (wid & 1) * 64;
    int n0 = blockIdx.x * 128, b = blockIdx.y;
    const bf16* aH = g_xcH + ((size_t)b * K2C + 128) * N_;  // x rows, k contig
    const bf16* aL = g_xcL + ((size_t)b * K2C + 128) * N_;
    const bf16* bH = g_adjH + (size_t)b * N_ * N_ + n0;
    const bf16* bL = g_adjL + (size_t)b * N_ * N_ + n0;
    float acc[2][8][4] = {};
    gemm_main<true, false>(sb, aH, aL, N_, bH, bL, N_, 32, tid, wm, wn, lane, acc);
    bf16* oH = g_y1H + (size_t)b * C_ * N_;
    bf16* oL = g_y1L + (size_t)b * C_ * N_;
#pragma unroll
    for (int mf = 0; mf < 2; ++mf) {
        int r = wm + mf * 16 + (lane >> 2);
#pragma unroll
        for (int nf = 0; nf < 8; ++nf) {
            int c = wn + nf * 8 + (lane & 3) * 2;
            const float* a = acc[mf][nf];
#pragma unroll
            for (int hrow = 0; hrow < 2; ++hrow) {
                int rr = r + hrow * 8;
                float v0 = leaky(a[hrow * 2 + 0]);
                float v1 = leaky(a[hrow * 2 + 1]);
                bf16 h0, l0, h1, l1;
                split1(v0, h0, l0);
                split1(v1, h1, l1);
                size_t off = (size_t)rr * N_ + n0 + c;
                *reinterpret_cast<u32*>(oH + off) = packbf2(h0, h1);
                *reinterpret_cast<u32*>(oL + off) = packbf2(l0, l1);
            }
        }
    }
}

// ---------------- y = leaky(w_dyn @ y1 + b_dyn) -> out f32 -------------------
__global__ void __launch_bounds__(256) k_y2_tc(const float* __restrict__ b_dyn,
                                               float* __restrict__ out) {
    extern __shared__ __align__(1024) char sm[];
    u32 sb = smem_u32(sm);
    int tid = threadIdx.x, wid = tid >> 5, lane = tid & 31;
    int wm = (wid >> 1) * 32, wn = (wid & 1) * 64;
    int n0 = blockIdx.x * 128, b = blockIdx.y;
    const bf16* bH = g_y1H + (size_t)b * C_ * N_ + n0;
    const bf16* bL = g_y1L + (size_t)b * C_ * N_ + n0;
    float acc[2][8][4] = {};
    gemm_main<true, false>(sb, g_wdynH, g_wdynL, C_, bH, bL, N_, 2, tid, wm, wn,
                           lane, acc);
    float* ob = out + (size_t)b * C_ * N_;
#pragma unroll
    for (int mf = 0; mf < 2; ++mf) {
        int r = wm + mf * 16 + (lane >> 2);
#pragma unroll
        for (int nf = 0; nf < 8; ++nf) {
            int c = wn + nf * 8 + (lane & 3) * 2;
            const float* a = acc[mf][nf];
#pragma unroll
            for (int hrow = 0; hrow < 2; ++hrow) {
                int rr = r + hrow * 8;
                float bias = b_dyn[rr];
                *reinterpret_cast<float2*>(ob + (size_t)rr * N_ + n0 + c) =
                    make_float2(leaky(a[hrow * 2 + 0] + bias),
                                leaky(a[hrow * 2 + 1] + bias));
            }
        }
    }
}

// ---------------- launch ----------------
extern "C" void kernel_launch(void* const* d_in, const int* in_sizes, int n_in,
                              void* d_out, int out_size) {
    const float* x     = (const float*)d_in[0];  // [8,128,2048]
    const float* w_adj = (const float*)d_in[1];  // [2048,256]
    const float* b_adj = (const float*)d_in[2];  // [2048]
    const float* w_dyn = (const float*)d_in[3];  // [128,128]
    const float* b_dyn = (const float*)d_in[4];  // [128]
    const float* gamma = (const float*)d_in[5];  // [1]
    float* out = (float*)d_out;                  // [8,128,2048]

    cudaFuncSetAttribute(k_energy_tc, cudaFuncAttributeMaxDynamicSharedMemorySize, SMEM_SZ);
    cudaFuncSetAttribute(k_xglb_tc, cudaFuncAttributeMaxDynamicSharedMemorySize, SMEM_SZ);
    cudaFuncSetAttribute(k_adj_tc, cudaFuncAttributeMaxDynamicSharedMemorySize, SMEM_SZ);
    cudaFuncSetAttribute(k_y1_tc, cudaFuncAttributeMaxDynamicSharedMemorySize, SMEM_SZ);
    cudaFuncSetAttribute(k_y2_tc, cudaFuncAttributeMaxDynamicSharedMemorySize, SMEM_SZ);

    k_cvt<<<1024, 256>>>(w_adj, w_dyn, x);
    k_energy_tc<<<dim3(KSPLIT, B_), 256, SMEM_SZ>>>();
    k_softmax<<<256, 128>>>();
    k_xglb_tc<<<dim3(N_ / 128, B_), 256, SMEM_SZ>>>(x, gamma);
    k_adj_tc<<<dim3(N_ / 128, N_ / 128, B_), 256, SMEM_SZ>>>(b_adj);
    k_y1_tc<<<dim3(N_ / 128, B_), 256, SMEM_SZ>>>();
    k_y2_tc<<<dim3(N_ / 128, B_), 256, SMEM_SZ>>>(b_dyn, out);
}

// round 7
// speedup vs baseline: 2.3812x; 1.0729x over previous
#include <cuda_runtime.h>
#include <cuda_bf16.h>
#include <cstdint>
#include <math.h>

#define B_ 8
#define C_ 128
#define N_ 2048
#define K2C 256
#define KSPLIT 16
#define SLOPE 0.2f

typedef unsigned int u32;
typedef unsigned long long u64;
typedef __nv_bfloat16 bf16;

// ---------------- device scratch (allocation-free) ----------------
__device__ float g_epart[KSPLIT * B_ * C_ * C_];                    // energy partials
__device__ bf16 g_xcH[B_ * K2C * N_], g_xcL[B_ * K2C * N_];         // xc = [x_glb; x]
__device__ bf16 g_wadjH[N_ * K2C], g_wadjL[N_ * K2C];
__device__ bf16 g_wdynH[C_ * C_], g_wdynL[C_ * C_];
__device__ bf16 g_attH[B_ * C_ * C_], g_attL[B_ * C_ * C_];
__device__ bf16 g_adjH[(size_t)B_ * N_ * N_], g_adjL[(size_t)B_ * N_ * N_];
__device__ bf16 g_y1H[B_ * C_ * N_], g_y1L[B_ * C_ * N_];

// ---------------- primitives ----------------
__device__ __forceinline__ u32 smem_u32(const void* p) {
    u32 a;
    asm("{ .reg .u64 t; cvta.to.shared.u64 t, %1; cvt.u32.u64 %0, t; }"
        : "=r"(a) : "l"(p));
    return a;
}
__device__ __forceinline__ void ldsm4(u32* r, u32 addr) {
    asm volatile("ldmatrix.sync.aligned.m8n8.x4.shared.b16 {%0,%1,%2,%3}, [%4];"
                 : "=r"(r[0]), "=r"(r[1]), "=r"(r[2]), "=r"(r[3]) : "r"(addr));
}
__device__ __forceinline__ void ldsm4t(u32* r, u32 addr) {
    asm volatile("ldmatrix.sync.aligned.m8n8.x4.trans.shared.b16 {%0,%1,%2,%3}, [%4];"
                 : "=r"(r[0]), "=r"(r[1]), "=r"(r[2]), "=r"(r[3]) : "r"(addr));
}
__device__ __forceinline__ void mma_bf16(float* c, const u32* a, const u32* b) {
    asm volatile(
        "mma.sync.aligned.m16n8k16.row.col.f32.bf16.bf16.f32 "
        "{%0,%1,%2,%3}, {%4,%5,%6,%7}, {%8,%9}, {%0,%1,%2,%3};"
        : "+f"(c[0]), "+f"(c[1]), "+f"(c[2]), "+f"(c[3])
        : "r"(a[0]), "r"(a[1]), "r"(a[2]), "r"(a[3]), "r"(b[0]), "r"(b[1]));
}
__device__ __forceinline__ void cpa16(u32 dst, const void* src) {
    asm volatile("cp.async.cg.shared.global [%0], [%1], 16;" :: "r"(dst), "l"(src));
}
#define CP_COMMIT() asm volatile("cp.async.commit_group;" ::: "memory")
#define CP_WAIT0() asm volatile("cp.async.wait_group 0;" ::: "memory")

#define SWZ(o) ((o) ^ (((o) >> 3) & 0x70))

// smem: single buffer: AH, AL [m][k] 128x64 (16KB each); BH, BL [k][n] 64x128
#define SM_AH 0
#define SM_AL 16384
#define SM_BH 32768
#define SM_BL 49152
#define SMEM_SZ 65536

__device__ __forceinline__ void split1(float v, bf16& h, bf16& l) {
    h = __float2bfloat16_rn(v);
    l = __float2bfloat16_rn(v - __bfloat162float(h));
}
__device__ __forceinline__ u32 packbf2(bf16 a, bf16 b) {
    return (u32)__bfloat16_as_ushort(a) | ((u32)__bfloat16_as_ushort(b) << 16);
}
__device__ __forceinline__ float leaky(float v) { return v > 0.0f ? v : SLOPE * v; }
__device__ __forceinline__ float sigm(float v) { return 1.0f / (1.0f + __expf(-v)); }

// Stage A-type tile (128 rows x 64 k) from bf16 row-major src, SW128 swizzle.
__device__ __forceinline__ void stA(u32 sbase, const bf16* __restrict__ src,
                                    int lda, int tid) {
    int row = tid & 127, g = tid >> 7;
    const bf16* p = src + (size_t)row * lda + g * 32;
#pragma unroll
    for (int i = 0; i < 4; ++i) {
        int ch = g * 4 + i;
        cpa16(sbase + (u32)SWZ(row * 128 + ch * 16), p + i * 8);
    }
}
// Stage B-type tile (64 k rows x 128 n) from bf16 [k][n] src, XOR chunk swizzle.
__device__ __forceinline__ void stB(u32 sbase, const bf16* __restrict__ src,
                                    int ldb, int tid) {
    int kr = tid >> 2, q = tid & 3;
    const bf16* p = src + (size_t)kr * ldb + q * 32;
#pragma unroll
    for (int i = 0; i < 4; ++i) {
        int ch = q * 4 + i;
        cpa16(sbase + (u32)(kr * 256 + ((ch ^ (kr & 15)) & 15) * 16), p + i * 8);
    }
}

// One 64-k chunk of split-precision MMAs. Warp tile 32(m) x 64(n).
template <bool BTRANS, bool FOUR>
__device__ __forceinline__ void chunk_mma(u32 sAH, u32 sAL, u32 sBH, u32 sBL,
                                          int wm, int wn, int lane,
                                          float acc[2][8][4]) {
#pragma unroll
    for (int s = 0; s < 4; ++s) {
        int k0 = s * 16;
        u32 ah[2][4], al[2][4];
        {
            int am = lane & 15, ak = k0 + (lane >> 4) * 8;
            u32 o0 = (u32)SWZ((wm + am) * 128 + ak * 2);
            u32 o1 = (u32)SWZ((wm + 16 + am) * 128 + ak * 2);
            ldsm4(ah[0], sAH + o0);
            ldsm4(ah[1], sAH + o1);
            ldsm4(al[0], sAL + o0);
            ldsm4(al[1], sAL + o1);
        }
#pragma unroll
        for (int g = 0; g < 4; ++g) {
            u32 bh[4], bl[4];
            if (BTRANS) {
                int t = lane >> 3, r = lane & 7;
                int k = k0 + (t & 1) * 8 + r;
                int nc = ((wn + g * 16) >> 3) + (t >> 1);
                u32 boff = (u32)(k * 256 + ((nc ^ (k & 15)) & 15) * 16);
                ldsm4t(bh, sBH + boff);
                ldsm4t(bl, sBL + boff);
            } else {
                int t = lane >> 3, r = lane & 7;
                int n = wn + g * 16 + (t >> 1) * 8 + r;
                int k = k0 + (t & 1) * 8;
                u32 boff = (u32)SWZ(n * 128 + k * 2);
                ldsm4(bh, sBH + boff);
                ldsm4(bl, sBL + boff);
            }
#pragma unroll
            for (int mf = 0; mf < 2; ++mf)
#pragma unroll
                for (int nf = 0; nf < 2; ++nf) {
                    float* c = acc[mf][g * 2 + nf];
                    mma_bf16(c, ah[mf], bh + nf * 2);
                    mma_bf16(c, ah[mf], bl + nf * 2);
                    mma_bf16(c, al[mf], bh + nf * 2);
                    if (FOUR) mma_bf16(c, al[mf], bl + nf * 2);
                }
        }
    }
}

// Single-buffered mainloop (2 CTAs/SM provide the overlap).
template <bool BTRANS, bool FOUR>
__device__ __forceinline__ void gemm_main(u32 sb, const bf16* aH, const bf16* aL,
                                          int lda, const bf16* bH, const bf16* bL,
                                          int ldb, int nc_total, int tid, int wm,
                                          int wn, int lane, float acc[2][8][4]) {
#pragma unroll 1
    for (int kc = 0; kc < nc_total; ++kc) {
        stA(sb + SM_AH, aH + (size_t)kc * 64, lda, tid);
        stA(sb + SM_AL, aL + (size_t)kc * 64, lda, tid);
        if (BTRANS) {
            stB(sb + SM_BH, bH + (size_t)kc * 64 * ldb, ldb, tid);
            stB(sb + SM_BL, bL + (size_t)kc * 64 * ldb, ldb, tid);
        }
        CP_COMMIT();
        CP_WAIT0();
        __syncthreads();
        u32 sbh = BTRANS ? sb + SM_BH : sb + SM_AH;
        u32 sbl = BTRANS ? sb + SM_BL : sb + SM_AL;
        chunk_mma<BTRANS, FOUR>(sb + SM_AH, sb + SM_AL, sbh, sbl, wm, wn, lane,
                                acc);
        __syncthreads();
    }
}

// ---------------- pre-pass: convert weights + x to bf16 hi/lo ----------------
__global__ void k_cvt(const float* __restrict__ w_adj,
                      const float* __restrict__ w_dyn,
                      const float* __restrict__ x) {
    int i0 = blockIdx.x * blockDim.x + threadIdx.x;
    int st = gridDim.x * blockDim.x;
    bf16 h, l;
    for (int i = i0; i < N_ * K2C; i += st) {
        split1(w_adj[i], h, l);
        g_wadjH[i] = h;
        g_wadjL[i] = l;
    }
    for (int i = i0; i < C_ * C_; i += st) {
        split1(w_dyn[i], h, l);
        g_wdynH[i] = h;
        g_wdynL[i] = l;
    }
    for (int i = i0; i < B_ * C_ * N_; i += st) {
        int b = i / (C_ * N_);
        int rem = i - b * C_ * N_;
        size_t dst = (size_t)b * K2C * N_ + 128 * N_ + rem;  // xc rows 128..255 = x
        split1(x[i], h, l);
        g_xcH[dst] = h;
        g_xcL[dst] = l;
    }
}

// ---------------- energy partials: E_part[ks][b] = x_ks @ x_ks^T (bf16x4) ----
__global__ void __launch_bounds__(256, 2) k_energy_tc() {
    extern __shared__ __align__(1024) char sm[];
    u32 sb = smem_u32(sm);
    int tid = threadIdx.x, wid = tid >> 5, lane = tid & 31;
    int wm = (wid >> 1) * 32, wn = (wid & 1) * 64;
    int ks = blockIdx.x, b = blockIdx.y;
    const bf16* aH = g_xcH + ((size_t)b * K2C + 128) * N_ + ks * 128;
    const bf16* aL = g_xcL + ((size_t)b * K2C + 128) * N_ + ks * 128;
    float acc[2][8][4] = {};
    gemm_main<false, true>(sb, aH, aL, N_, aH, aL, 0, 2, tid, wm, wn, lane, acc);
    float* out = g_epart + ((size_t)(ks * B_ + b) * C_) * C_;
#pragma unroll
    for (int mf = 0; mf < 2; ++mf) {
        int r = wm + mf * 16 + (lane >> 2);
#pragma unroll
        for (int nf = 0; nf < 8; ++nf) {
            int c = wn + nf * 8 + (lane & 3) * 2;
            const float* a = acc[mf][nf];
            *reinterpret_cast<float2*>(out + r * C_ + c) = make_float2(a[0], a[1]);
            *reinterpret_cast<float2*>(out + (r + 8) * C_ + c) = make_float2(a[2], a[3]);
        }
    }
}

// ---------------- softmax(-energy) -> att bf16 hi/lo -------------------------
__global__ void __launch_bounds__(128) k_softmax() {
    int warp = threadIdx.x >> 5, lane = threadIdx.x & 31;
    int row = blockIdx.x * 4 + warp;
    int b = row >> 7, c = row & 127;
    float e[4];
#pragma unroll
    for (int q = 0; q < 4; ++q) {
        int d = lane + q * 32;
        float s = 0.0f;
#pragma unroll
        for (int p = 0; p < KSPLIT; ++p)
            s += g_epart[((p * B_ + b) * C_ + c) * C_ + d];
        e[q] = -s;
    }
    float m = fmaxf(fmaxf(e[0], e[1]), fmaxf(e[2], e[3]));
#pragma unroll
    for (int off = 16; off > 0; off >>= 1)
        m = fmaxf(m, __shfl_xor_sync(0xffffffffu, m, off));
    float p4[4], s = 0.0f;
#pragma unroll
    for (int q = 0; q < 4; ++q) {
        p4[q] = __expf(e[q] - m);
        s += p4[q];
    }
#pragma unroll
    for (int off = 16; off > 0; off >>= 1)
        s += __shfl_xor_sync(0xffffffffu, s, off);
    float inv = 1.0f / s;
#pragma unroll
    for (int q = 0; q < 4; ++q) {
        bf16 h, l;
        split1(p4[q] * inv, h, l);
        g_attH[(b * C_ + c) * C_ + lane + q * 32] = h;
        g_attL[(b * C_ + c) * C_ + lane + q * 32] = l;
    }
}

// ---------------- x_glb = gamma*(att @ x) + x -> xc rows 0..127 --------------
__global__ void __launch_bounds__(256, 2) k_xglb_tc(const float* __restrict__ x,
                                                    const float* __restrict__ gamma) {
    extern __shared__ __align__(1024) char sm[];
    u32 sb = smem_u32(sm);
    int tid = threadIdx.x, wid = tid >> 5, lane = tid & 31;
    int wm = (wid >> 1) * 32, wn = (wid & 1) * 64;
    int n0 = blockIdx.x * 128, b = blockIdx.y;
    const bf16* aH = g_attH + (size_t)b * C_ * C_;
    const bf16* aL = g_attL + (size_t)b * C_ * C_;
    const bf16* bH = g_xcH + ((size_t)b * K2C + 128) * N_ + n0;
    const bf16* bL = g_xcL + ((size_t)b * K2C + 128) * N_ + n0;
    float acc[2][8][4] = {};
    gemm_main<true, false>(sb, aH, aL, C_, bH, bL, N_, 2, tid, wm, wn, lane, acc);
    float gm = *gamma;
    const float* xb = x + (size_t)b * C_ * N_;
    bf16* oH = g_xcH + (size_t)b * K2C * N_;
    bf16* oL = g_xcL + (size_t)b * K2C * N_;
#pragma unroll
    for (int mf = 0; mf < 2; ++mf) {
        int r = wm + mf * 16 + (lane >> 2);
#pragma unroll
        for (int nf = 0; nf < 8; ++nf) {
            int c = wn + nf * 8 + (lane & 3) * 2;
            const float* a = acc[mf][nf];
#pragma unroll
            for (int hrow = 0; hrow < 2; ++hrow) {
                int rr = r + hrow * 8;
                float v0 = fmaf(gm, a[hrow * 2 + 0], xb[(size_t)rr * N_ + n0 + c]);
                float v1 = fmaf(gm, a[hrow * 2 + 1], xb[(size_t)rr * N_ + n0 + c + 1]);
                bf16 h0, l0, h1, l1;
                split1(v0, h0, l0);
                split1(v1, h1, l1);
                *reinterpret_cast<u32*>(oH + (size_t)rr * N_ + n0 + c) = packbf2(h0, h1);
                *reinterpret_cast<u32*>(oL + (size_t)rr * N_ + n0 + c) = packbf2(l0, l1);
            }
        }
    }
}

// ---------------- adj = sigmoid(w_adj @ xc + b_adj) -> bf16 hi/lo ------------
__global__ void __launch_bounds__(256, 2) k_adj_tc(const float* __restrict__ b_adj) {
    extern __shared__ __align__(1024) char sm[];
    u32 sb = smem_u32(sm);
    int tid = threadIdx.x, wid = tid >> 5, lane = tid & 31;
    int wm = (wid >> 1) * 32, wn = (wid & 1) * 64;
    int n0 = blockIdx.x * 128, m0 = blockIdx.y * 128, b = blockIdx.z;
    const bf16* aH = g_wadjH + (size_t)m0 * K2C;
    const bf16* aL = g_wadjL + (size_t)m0 * K2C;
    const bf16* bH = g_xcH + (size_t)b * K2C * N_ + n0;
    const bf16* bL = g_xcL + (size_t)b * K2C * N_ + n0;
    float acc[2][8][4] = {};
    gemm_main<true, false>(sb, aH, aL, K2C, bH, bL, N_, 4, tid, wm, wn, lane, acc);
    bf16* oH = g_adjH + (size_t)b * N_ * N_;
    bf16* oL = g_adjL + (size_t)b * N_ * N_;
#pragma unroll
    for (int mf = 0; mf < 2; ++mf) {
        int r = wm + mf * 16 + (lane >> 2);
#pragma unroll
        for (int nf = 0; nf < 8; ++nf) {
            int c = wn + nf * 8 + (lane & 3) * 2;
            const float* a = acc[mf][nf];
#pragma unroll
            for (int hrow = 0; hrow < 2; ++hrow) {
                int rr = r + hrow * 8;
                float bias = b_adj[m0 + rr];
                float v0 = sigm(a[hrow * 2 + 0] + bias);
                float v1 = sigm(a[hrow * 2 + 1] + bias);
                bf16 h0, l0, h1, l1;
                split1(v0, h0, l0);
                split1(v1, h1, l1);
                size_t off = (size_t)(m0 + rr) * N_ + n0 + c;
                *reinterpret_cast<u32*>(oH + off) = packbf2(h0, h1);
                *reinterpret_cast<u32*>(oL + off) = packbf2(l0, l1);
            }
        }
    }
}

// ---------------- y1 = leaky(x @ adj) -> bf16 hi/lo ---------------------------
__global__ void __launch_bounds__(256, 2) k_y1_tc() {
    extern __shared__ __align__(1024) char sm[];
    u32 sb = smem_u32(sm);
    int tid = threadIdx.x, wid = tid >> 5, lane = tid & 31;
    int wm = (wid >> 1) * 32, wn = (wid & 1) * 64;
    int n0 = blockIdx.x * 128, b = blockIdx.y;
    const bf16* aH = g_xcH + ((size_t)b * K2C + 128) * N_;  // x rows, k contig
    const bf16* aL = g_xcL + ((size_t)b * K2C + 128) * N_;
    const bf16* bH = g_adjH + (size_t)b * N_ * N_ + n0;
    const bf16* bL = g_adjL + (size_t)b * N_ * N_ + n0;
    float acc[2][8][4] = {};
    gemm_main<true, false>(sb, aH, aL, N_, bH, bL, N_, 32, tid, wm, wn, lane, acc);
    bf16* oH = g_y1H + (size_t)b * C_ * N_;
    bf16* oL = g_y1L + (size_t)b * C_ * N_;
#pragma unroll
    for (int mf = 0; mf < 2; ++mf) {
        int r = wm + mf * 16 + (lane >> 2);
#pragma unroll
        for (int nf = 0; nf < 8; ++nf) {
            int c = wn + nf * 8 + (lane & 3) * 2;
            const float* a = acc[mf][nf];
#pragma unroll
            for (int hrow = 0; hrow < 2; ++hrow) {
                int rr = r + hrow * 8;
                float v0 = leaky(a[hrow * 2 + 0]);
                float v1 = leaky(a[hrow * 2 + 1]);
                bf16 h0, l0, h1, l1;
                split1(v0, h0, l0);
                split1(v1, h1, l1);
                size_t off = (size_t)rr * N_ + n0 + c;
                *reinterpret_cast<u32*>(oH + off) = packbf2(h0, h1);
                *reinterpret_cast<u32*>(oL + off) = packbf2(l0, l1);
            }
        }
    }
}

// ---------------- y = leaky(w_dyn @ y1 + b_dyn) -> out f32 -------------------
__global__ void __launch_bounds__(256, 2) k_y2_tc(const float* __restrict__ b_dyn,
                                                  float* __restrict__ out) {
    extern __shared__ __align__(1024) char sm[];
    u32 sb = smem_u32(sm);
    int tid = threadIdx.x, wid = tid >> 5, lane = tid & 31;
    int wm = (wid >> 1) * 32, wn = (wid & 1) * 64;
    int n0 = blockIdx.x * 128, b = blockIdx.y;
    const bf16* bH = g_y1H + (size_t)b * C_ * N_ + n0;
    const bf16* bL = g_y1L + (size_t)b * C_ * N_ + n0;
    float acc[2][8][4] = {};
    gemm_main<true, false>(sb, g_wdynH, g_wdynL, C_, bH, bL, N_, 2, tid, wm, wn,
                           lane, acc);
    float* ob = out + (size_t)b * C_ * N_;
#pragma unroll
    for (int mf = 0; mf < 2; ++mf) {
        int r = wm + mf * 16 + (lane >> 2);
#pragma unroll
        for (int nf = 0; nf < 8; ++nf) {
            int c = wn + nf * 8 + (lane & 3) * 2;
            const float* a = acc[mf][nf];
#pragma unroll
            for (int hrow = 0; hrow < 2; ++hrow) {
                int rr = r + hrow * 8;
                float bias = b_dyn[rr];
                *reinterpret_cast<float2*>(ob + (size_t)rr * N_ + n0 + c) =
                    make_float2(leaky(a[hrow * 2 + 0] + bias),
                                leaky(a[hrow * 2 + 1] + bias));
            }
        }
    }
}

// ---------------- launch ----------------
extern "C" void kernel_launch(void* const* d_in, const int* in_sizes, int n_in,
                              void* d_out, int out_size) {
    const float* x     = (const float*)d_in[0];  // [8,128,2048]
    const float* w_adj = (const float*)d_in[1];  // [2048,256]
    const float* b_adj = (const float*)d_in[2];  // [2048]
    const float* w_dyn = (const float*)d_in[3];  // [128,128]
    const float* b_dyn = (const float*)d_in[4];  // [128]
    const float* gamma = (const float*)d_in[5];  // [1]
    float* out = (float*)d_out;                  // [8,128,2048]

    cudaFuncSetAttribute(k_energy_tc, cudaFuncAttributeMaxDynamicSharedMemorySize, SMEM_SZ);
    cudaFuncSetAttribute(k_xglb_tc, cudaFuncAttributeMaxDynamicSharedMemorySize, SMEM_SZ);
    cudaFuncSetAttribute(k_adj_tc, cudaFuncAttributeMaxDynamicSharedMemorySize, SMEM_SZ);
    cudaFuncSetAttribute(k_y1_tc, cudaFuncAttributeMaxDynamicSharedMemorySize, SMEM_SZ);
    cudaFuncSetAttribute(k_y2_tc, cudaFuncAttributeMaxDynamicSharedMemorySize, SMEM_SZ);

    k_cvt<<<1024, 256>>>(w_adj, w_dyn, x);
    k_energy_tc<<<dim3(KSPLIT, B_), 256, SMEM_SZ>>>();
    k_softmax<<<256, 128>>>();
    k_xglb_tc<<<dim3(N_ / 128, B_), 256, SMEM_SZ>>>(x, gamma);
    k_adj_tc<<<dim3(N_ / 128, N_ / 128, B_), 256, SMEM_SZ>>>(b_adj);
    k_y1_tc<<<dim3(N_ / 128, B_), 256, SMEM_SZ>>>();
    k_y2_tc<<<dim3(N_ / 128, B_), 256, SMEM_SZ>>>(b_dyn, out);
}

// round 8
// speedup vs baseline: 2.5665x; 1.0778x over previous
#include <cuda_runtime.h>
#include <cuda_bf16.h>
#include <cstdint>
#include <math.h>

#define B_ 8
#define C_ 128
#define N_ 2048
#define K2C 256
#define KSPLIT 16
#define SLOPE 0.2f

typedef unsigned int u32;
typedef unsigned long long u64;
typedef __nv_bfloat16 bf16;

// ---------------- device scratch (allocation-free) ----------------
__device__ float g_epart[KSPLIT * B_ * C_ * C_];                    // energy partials
__device__ bf16 g_xcH[B_ * K2C * N_], g_xcL[B_ * K2C * N_];         // xc = [x_glb; x]
__device__ bf16 g_wadjH[N_ * K2C], g_wadjL[N_ * K2C];
__device__ bf16 g_wdynH[C_ * C_], g_wdynL[C_ * C_];
__device__ bf16 g_attH[B_ * C_ * C_], g_attL[B_ * C_ * C_];
__device__ bf16 g_adjH[(size_t)B_ * N_ * N_], g_adjL[(size_t)B_ * N_ * N_];
__device__ bf16 g_y1H[B_ * C_ * N_], g_y1L[B_ * C_ * N_];

// ---------------- primitives ----------------
__device__ __forceinline__ u32 smem_u32(const void* p) {
    u32 a;
    asm("{ .reg .u64 t; cvta.to.shared.u64 t, %1; cvt.u32.u64 %0, t; }"
        : "=r"(a) : "l"(p));
    return a;
}
__device__ __forceinline__ void ldsm4(u32* r, u32 addr) {
    asm volatile("ldmatrix.sync.aligned.m8n8.x4.shared.b16 {%0,%1,%2,%3}, [%4];"
                 : "=r"(r[0]), "=r"(r[1]), "=r"(r[2]), "=r"(r[3]) : "r"(addr));
}
__device__ __forceinline__ void ldsm4t(u32* r, u32 addr) {
    asm volatile("ldmatrix.sync.aligned.m8n8.x4.trans.shared.b16 {%0,%1,%2,%3}, [%4];"
                 : "=r"(r[0]), "=r"(r[1]), "=r"(r[2]), "=r"(r[3]) : "r"(addr));
}
__device__ __forceinline__ void mma_bf16(float* c, const u32* a, const u32* b) {
    asm volatile(
        "mma.sync.aligned.m16n8k16.row.col.f32.bf16.bf16.f32 "
        "{%0,%1,%2,%3}, {%4,%5,%6,%7}, {%8,%9}, {%0,%1,%2,%3};"
        : "+f"(c[0]), "+f"(c[1]), "+f"(c[2]), "+f"(c[3])
        : "r"(a[0]), "r"(a[1]), "r"(a[2]), "r"(a[3]), "r"(b[0]), "r"(b[1]));
}
__device__ __forceinline__ void cpa16(u32 dst, const void* src) {
    asm volatile("cp.async.cg.shared.global [%0], [%1], 16;" :: "r"(dst), "l"(src));
}
#define CP_COMMIT() asm volatile("cp.async.commit_group;" ::: "memory")
#define CP_WAIT1() asm volatile("cp.async.wait_group 1;" ::: "memory")
#define CP_WAIT0() asm volatile("cp.async.wait_group 0;" ::: "memory")

#define SWZ(o) ((o) ^ (((o) >> 3) & 0x70))

// smem: A single buffer (H,L); B double buffer (H,L per buf)
#define SM_AH 0
#define SM_AL 16384
#define SM_BH(buf) (32768 + (buf) * 32768)
#define SM_BL(buf) (49152 + (buf) * 32768)
#define SMEM_SZ 98304

__device__ __forceinline__ void split1(float v, bf16& h, bf16& l) {
    h = __float2bfloat16_rn(v);
    l = __float2bfloat16_rn(v - __bfloat162float(h));
}
__device__ __forceinline__ u32 packbf2(bf16 a, bf16 b) {
    return (u32)__bfloat16_as_ushort(a) | ((u32)__bfloat16_as_ushort(b) << 16);
}
__device__ __forceinline__ float leaky(float v) { return v > 0.0f ? v : SLOPE * v; }
__device__ __forceinline__ float sigm(float v) { return 1.0f / (1.0f + __expf(-v)); }

// Stage A-type tile (128 rows x 64 k) from bf16 row-major src, SW128 swizzle.
__device__ __forceinline__ void stA(u32 sbase, const bf16* __restrict__ src,
                                    int lda, int tid) {
    int row = tid & 127, g = tid >> 7;
    const bf16* p = src + (size_t)row * lda + g * 32;
#pragma unroll
    for (int i = 0; i < 4; ++i) {
        int ch = g * 4 + i;
        cpa16(sbase + (u32)SWZ(row * 128 + ch * 16), p + i * 8);
    }
}
// Stage B-type tile (64 k rows x 128 n) from bf16 [k][n] src, XOR chunk swizzle.
__device__ __forceinline__ void stB(u32 sbase, const bf16* __restrict__ src,
                                    int ldb, int tid) {
    int kr = tid >> 2, q = tid & 3;
    const bf16* p = src + (size_t)kr * ldb + q * 32;
#pragma unroll
    for (int i = 0; i < 4; ++i) {
        int ch = q * 4 + i;
        cpa16(sbase + (u32)(kr * 256 + ((ch ^ (kr & 15)) & 15) * 16), p + i * 8);
    }
}

// One 64-k chunk of split-precision MMAs. Warp tile 32(m) x 64(n).
template <bool BTRANS, bool FOUR>
__device__ __forceinline__ void chunk_mma(u32 sAH, u32 sAL, u32 sBH, u32 sBL,
                                          int wm, int wn, int lane,
                                          float acc[2][8][4]) {
#pragma unroll
    for (int s = 0; s < 4; ++s) {
        int k0 = s * 16;
        u32 ah[2][4], al[2][4];
        {
            int am = lane & 15, ak = k0 + (lane >> 4) * 8;
            u32 o0 = (u32)SWZ((wm + am) * 128 + ak * 2);
            u32 o1 = (u32)SWZ((wm + 16 + am) * 128 + ak * 2);
            ldsm4(ah[0], sAH + o0);
            ldsm4(ah[1], sAH + o1);
            ldsm4(al[0], sAL + o0);
            ldsm4(al[1], sAL + o1);
        }
#pragma unroll
        for (int g = 0; g < 4; ++g) {
            u32 bh[4], bl[4];
            if (BTRANS) {
                int t = lane >> 3, r = lane & 7;
                int k = k0 + (t & 1) * 8 + r;
                int nc = ((wn + g * 16) >> 3) + (t >> 1);
                u32 boff = (u32)(k * 256 + ((nc ^ (k & 15)) & 15) * 16);
                ldsm4t(bh, sBH + boff);
                ldsm4t(bl, sBL + boff);
            } else {
                int t = lane >> 3, r = lane & 7;
                int n = wn + g * 16 + (t >> 1) * 8 + r;
                int k = k0 + (t & 1) * 8;
                u32 boff = (u32)SWZ(n * 128 + k * 2);
                ldsm4(bh, sBH + boff);
                ldsm4(bl, sBL + boff);
            }
#pragma unroll
            for (int mf = 0; mf < 2; ++mf)
#pragma unroll
                for (int nf = 0; nf < 2; ++nf) {
                    float* c = acc[mf][g * 2 + nf];
                    mma_bf16(c, ah[mf], bh + nf * 2);
                    mma_bf16(c, ah[mf], bl + nf * 2);
                    mma_bf16(c, al[mf], bh + nf * 2);
                    if (FOUR) mma_bf16(c, al[mf], bl + nf * 2);
                }
        }
    }
}

// Pipelined mainloop: A staged one chunk ahead (right after its buffer frees),
// B double-buffered two chunks ahead. 2 CTAs/SM cover the barrier shadow.
template <bool BTRANS, bool FOUR>
__device__ __forceinline__ void gemm_main(u32 sb, const bf16* aH, const bf16* aL,
                                          int lda, const bf16* bH, const bf16* bL,
                                          int ldb, int nc_total, int tid, int wm,
                                          int wn, int lane, float acc[2][8][4]) {
    if (BTRANS) {
        stA(sb + SM_AH, aH, lda, tid);
        stA(sb + SM_AL, aL, lda, tid);
        stB(sb + SM_BH(0), bH, ldb, tid);
        stB(sb + SM_BL(0), bL, ldb, tid);
        CP_COMMIT();
        if (nc_total > 1) {
            stB(sb + SM_BH(1), bH + (size_t)64 * ldb, ldb, tid);
            stB(sb + SM_BL(1), bL + (size_t)64 * ldb, ldb, tid);
            CP_COMMIT();
        }
#pragma unroll 1
        for (int kc = 0; kc < nc_total; ++kc) {
            if (kc + 1 < nc_total) CP_WAIT1(); else CP_WAIT0();
            __syncthreads();
            int cb = kc & 1;
            chunk_mma<true, FOUR>(sb + SM_AH, sb + SM_AL, sb + SM_BH(cb),
                                  sb + SM_BL(cb), wm, wn, lane, acc);
            __syncthreads();
            if (kc + 1 < nc_total) {
                stA(sb + SM_AH, aH + (size_t)(kc + 1) * 64, lda, tid);
                stA(sb + SM_AL, aL + (size_t)(kc + 1) * 64, lda, tid);
                CP_COMMIT();
            }
            if (kc + 2 < nc_total) {
                stB(sb + SM_BH(cb), bH + (size_t)(kc + 2) * 64 * ldb, ldb, tid);
                stB(sb + SM_BL(cb), bL + (size_t)(kc + 2) * 64 * ldb, ldb, tid);
                CP_COMMIT();
            }
        }
    } else {
        // symmetric case (energy): B frags come from the A tile
#pragma unroll 1
        for (int kc = 0; kc < nc_total; ++kc) {
            stA(sb + SM_AH, aH + (size_t)kc * 64, lda, tid);
            stA(sb + SM_AL, aL + (size_t)kc * 64, lda, tid);
            CP_COMMIT();
            CP_WAIT0();
            __syncthreads();
            chunk_mma<false, FOUR>(sb + SM_AH, sb + SM_AL, sb + SM_AH,
                                   sb + SM_AL, wm, wn, lane, acc);
            __syncthreads();
        }
    }
}

// ---------------- pre-pass: convert weights + x to bf16 hi/lo ----------------
__global__ void k_cvt(const float* __restrict__ w_adj,
                      const float* __restrict__ w_dyn,
                      const float* __restrict__ x) {
    int i0 = blockIdx.x * blockDim.x + threadIdx.x;
    int st = gridDim.x * blockDim.x;
    bf16 h, l;
    for (int i = i0; i < N_ * K2C; i += st) {
        split1(w_adj[i], h, l);
        g_wadjH[i] = h;
        g_wadjL[i] = l;
    }
    for (int i = i0; i < C_ * C_; i += st) {
        split1(w_dyn[i], h, l);
        g_wdynH[i] = h;
        g_wdynL[i] = l;
    }
    for (int i = i0; i < B_ * C_ * N_; i += st) {
        int b = i / (C_ * N_);
        int rem = i - b * C_ * N_;
        size_t dst = (size_t)b * K2C * N_ + 128 * N_ + rem;  // xc rows 128..255 = x
        split1(x[i], h, l);
        g_xcH[dst] = h;
        g_xcL[dst] = l;
    }
}

// ---------------- energy partials: E_part[ks][b] = x_ks @ x_ks^T (bf16x4) ----
__global__ void __launch_bounds__(256, 2) k_energy_tc() {
    extern __shared__ __align__(1024) char sm[];
    u32 sb = smem_u32(sm);
    int tid = threadIdx.x, wid = tid >> 5, lane = tid & 31;
    int wm = (wid >> 1) * 32, wn = (wid & 1) * 64;
    int ks = blockIdx.x, b = blockIdx.y;
    const bf16* aH = g_xcH + ((size_t)b * K2C + 128) * N_ + ks * 128;
    const bf16* aL = g_xcL + ((size_t)b * K2C + 128) * N_ + ks * 128;
    float acc[2][8][4] = {};
    gemm_main<false, true>(sb, aH, aL, N_, aH, aL, 0, 2, tid, wm, wn, lane, acc);
    float* out = g_epart + ((size_t)(ks * B_ + b) * C_) * C_;
#pragma unroll
    for (int mf = 0; mf < 2; ++mf) {
        int r = wm + mf * 16 + (lane >> 2);
#pragma unroll
        for (int nf = 0; nf < 8; ++nf) {
            int c = wn + nf * 8 + (lane & 3) * 2;
            const float* a = acc[mf][nf];
            *reinterpret_cast<float2*>(out + r * C_ + c) = make_float2(a[0], a[1]);
            *reinterpret_cast<float2*>(out + (r + 8) * C_ + c) = make_float2(a[2], a[3]);
        }
    }
}

// ---------------- softmax(-energy) -> att bf16 hi/lo -------------------------
__global__ void __launch_bounds__(128) k_softmax() {
    int warp = threadIdx.x >> 5, lane = threadIdx.x & 31;
    int row = blockIdx.x * 4 + warp;
    int b = row >> 7, c = row & 127;
    float e[4];
#pragma unroll
    for (int q = 0; q < 4; ++q) {
        int d = lane + q * 32;
        float s = 0.0f;
#pragma unroll
        for (int p = 0; p < KSPLIT; ++p)
            s += g_epart[((p * B_ + b) * C_ + c) * C_ + d];
        e[q] = -s;
    }
    float m = fmaxf(fmaxf(e[0], e[1]), fmaxf(e[2], e[3]));
#pragma unroll
    for (int off = 16; off > 0; off >>= 1)
        m = fmaxf(m, __shfl_xor_sync(0xffffffffu, m, off));
    float p4[4], s = 0.0f;
#pragma unroll
    for (int q = 0; q < 4; ++q) {
        p4[q] = __expf(e[q] - m);
        s += p4[q];
    }
#pragma unroll
    for (int off = 16; off > 0; off >>= 1)
        s += __shfl_xor_sync(0xffffffffu, s, off);
    float inv = 1.0f / s;
#pragma unroll
    for (int q = 0; q < 4; ++q) {
        bf16 h, l;
        split1(p4[q] * inv, h, l);
        g_attH[(b * C_ + c) * C_ + lane + q * 32] = h;
        g_attL[(b * C_ + c) * C_ + lane + q * 32] = l;
    }
}

// ---------------- x_glb = gamma*(att @ x) + x -> xc rows 0..127 --------------
__global__ void __launch_bounds__(256, 2) k_xglb_tc(const float* __restrict__ x,
                                                    const float* __restrict__ gamma) {
    extern __shared__ __align__(1024) char sm[];
    u32 sb = smem_u32(sm);
    int tid = threadIdx.x, wid = tid >> 5, lane = tid & 31;
    int wm = (wid >> 1) * 32, wn = (wid & 1) * 64;
    int n0 = blockIdx.x * 128, b = blockIdx.y;
    const bf16* aH = g_attH + (size_t)b * C_ * C_;
    const bf16* aL = g_attL + (size_t)b * C_ * C_;
    const bf16* bH = g_xcH + ((size_t)b * K2C + 128) * N_ + n0;
    const bf16* bL = g_xcL + ((size_t)b * K2C + 128) * N_ + n0;
    float acc[2][8][4] = {};
    gemm_main<true, false>(sb, aH, aL, C_, bH, bL, N_, 2, tid, wm, wn, lane, acc);
    float gm = *gamma;
    const float* xb = x + (size_t)b * C_ * N_;
    bf16* oH = g_xcH + (size_t)b * K2C * N_;
    bf16* oL = g_xcL + (size_t)b * K2C * N_;
#pragma unroll
    for (int mf = 0; mf < 2; ++mf) {
        int r = wm + mf * 16 + (lane >> 2);
#pragma unroll
        for (int nf = 0; nf < 8; ++nf) {
            int c = wn + nf * 8 + (lane & 3) * 2;
            const float* a = acc[mf][nf];
#pragma unroll
            for (int hrow = 0; hrow < 2; ++hrow) {
                int rr = r + hrow * 8;
                float v0 = fmaf(gm, a[hrow * 2 + 0], xb[(size_t)rr * N_ + n0 + c]);
                float v1 = fmaf(gm, a[hrow * 2 + 1], xb[(size_t)rr * N_ + n0 + c + 1]);
                bf16 h0, l0, h1, l1;
                split1(v0, h0, l0);
                split1(v1, h1, l1);
                *reinterpret_cast<u32*>(oH + (size_t)rr * N_ + n0 + c) = packbf2(h0, h1);
                *reinterpret_cast<u32*>(oL + (size_t)rr * N_ + n0 + c) = packbf2(l0, l1);
            }
        }
    }
}

// ---------------- adj = sigmoid(w_adj @ xc + b_adj) -> bf16 hi/lo ------------
__global__ void __launch_bounds__(256, 2) k_adj_tc(const float* __restrict__ b_adj) {
    extern __shared__ __align__(1024) char sm[];
    u32 sb = smem_u32(sm);
    int tid = threadIdx.x, wid = tid >> 5, lane = tid & 31;
    int wm = (wid >> 1) * 32, wn = (wid & 1) * 64;
    int n0 = blockIdx.x * 128, m0 = blockIdx.y * 128, b = blockIdx.z;
    const bf16* aH = g_wadjH + (size_t)m0 * K2C;
    const bf16* aL = g_wadjL + (size_t)m0 * K2C;
    const bf16* bH = g_xcH + (size_t)b * K2C * N_ + n0;
    const bf16* bL = g_xcL + (size_t)b * K2C * N_ + n0;
    float acc[2][8][4] = {};
    gemm_main<true, false>(sb, aH, aL, K2C, bH, bL, N_, 4, tid, wm, wn, lane, acc);
    bf16* oH = g_adjH + (size_t)b * N_ * N_;
    bf16* oL = g_adjL + (size_t)b * N_ * N_;
#pragma unroll
    for (int mf = 0; mf < 2; ++mf) {
        int r = wm + mf * 16 + (lane >> 2);
#pragma unroll
        for (int nf = 0; nf < 8; ++nf) {
            int c = wn + nf * 8 + (lane & 3) * 2;
            const float* a = acc[mf][nf];
#pragma unroll
            for (int hrow = 0; hrow < 2; ++hrow) {
                int rr = r + hrow * 8;
                float bias = b_adj[m0 + rr];
                float v0 = sigm(a[hrow * 2 + 0] + bias);
                float v1 = sigm(a[hrow * 2 + 1] + bias);
                bf16 h0, l0, h1, l1;
                split1(v0, h0, l0);
                split1(v1, h1, l1);
                size_t off = (size_t)(m0 + rr) * N_ + n0 + c;
                *reinterpret_cast<u32*>(oH + off) = packbf2(h0, h1);
                *reinterpret_cast<u32*>(oL + off) = packbf2(l0, l1);
            }
        }
    }
}

// ---------------- y1 = leaky(x @ adj) -> bf16 hi/lo ---------------------------
__global__ void __launch_bounds__(256, 2) k_y1_tc() {
    extern __shared__ __align__(1024) char sm[];
    u32 sb = smem_u32(sm);
    int tid = threadIdx.x, wid = tid >> 5, lane = tid & 31;
    int wm = (wid >> 1) * 32, wn = (wid & 1) * 64;
    int n0 = blockIdx.x * 128, b = blockIdx.y;
    const bf16* aH = g_xcH + ((size_t)b * K2C + 128) * N_;  // x rows, k contig
    const bf16* aL = g_xcL + ((size_t)b * K2C + 128) * N_;
    const bf16* bH = g_adjH + (size_t)b * N_ * N_ + n0;
    const bf16* bL = g_adjL + (size_t)b * N_ * N_ + n0;
    float acc[2][8][4] = {};
    gemm_main<true, false>(sb, aH, aL, N_, bH, bL, N_, 32, tid, wm, wn, lane, acc);
    bf16* oH = g_y1H + (size_t)b * C_ * N_;
    bf16* oL = g_y1L + (size_t)b * C_ * N_;
#pragma unroll
    for (int mf = 0; mf < 2; ++mf) {
        int r = wm + mf * 16 + (lane >> 2);
#pragma unroll
        for (int nf = 0; nf < 8; ++nf) {
            int c = wn + nf * 8 + (lane & 3) * 2;
            const float* a = acc[mf][nf];
#pragma unroll
            for (int hrow = 0; hrow < 2; ++hrow) {
                int rr = r + hrow * 8;
                float v0 = leaky(a[hrow * 2 + 0]);
                float v1 = leaky(a[hrow * 2 + 1]);
                bf16 h0, l0, h1, l1;
                split1(v0, h0, l0);
                split1(v1, h1, l1);
                size_t off = (size_t)rr * N_ + n0 + c;
                *reinterpret_cast<u32*>(oH + off) = packbf2(h0, h1);
                *reinterpret_cast<u32*>(oL + off) = packbf2(l0, l1);
            }
        }
    }
}

// ---------------- y = leaky(w_dyn @ y1 + b_dyn) -> out f32 -------------------
__global__ void __launch_bounds__(256, 2) k_y2_tc(const float* __restrict__ b_dyn,
                                                  float* __restrict__ out) {
    extern __shared__ __align__(1024) char sm[];
    u32 sb = smem_u32(sm);
    int tid = threadIdx.x, wid = tid >> 5, lane = tid & 31;
    int wm = (wid >> 1) * 32, wn = (wid & 1) * 64;
    int n0 = blockIdx.x * 128, b = blockIdx.y;
    const bf16* bH = g_y1H + (size_t)b * C_ * N_ + n0;
    const bf16* bL = g_y1L + (size_t)b * C_ * N_ + n0;
    float acc[2][8][4] = {};
    gemm_main<true, false>(sb, g_wdynH, g_wdynL, C_, bH, bL, N_, 2, tid, wm, wn,
                           lane, acc);
    float* ob = out + (size_t)b * C_ * N_;
#pragma unroll
    for (int mf = 0; mf < 2; ++mf) {
        int r = wm + mf * 16 + (lane >> 2);
#pragma unroll
        for (int nf = 0; nf < 8; ++nf) {
            int c = wn + nf * 8 + (lane & 3) * 2;
            const float* a = acc[mf][nf];
#pragma unroll
            for (int hrow = 0; hrow < 2; ++hrow) {
                int rr = r + hrow * 8;
                float bias = b_dyn[rr];
                *reinterpret_cast<float2*>(ob + (size_t)rr * N_ + n0 + c) =
                    make_float2(leaky(a[hrow * 2 + 0] + bias),
                                leaky(a[hrow * 2 + 1] + bias));
            }
        }
    }
}

// ---------------- launch ----------------
extern "C" void kernel_launch(void* const* d_in, const int* in_sizes, int n_in,
                              void* d_out, int out_size) {
    const float* x     = (const float*)d_in[0];  // [8,128,2048]
    const float* w_adj = (const float*)d_in[1];  // [2048,256]
    const float* b_adj = (const float*)d_in[2];  // [2048]
    const float* w_dyn = (const float*)d_in[3];  // [128,128]
    const float* b_dyn = (const float*)d_in[4];  // [128]
    const float* gamma = (const float*)d_in[5];  // [1]
    float* out = (float*)d_out;                  // [8,128,2048]

    cudaFuncSetAttribute(k_energy_tc, cudaFuncAttributeMaxDynamicSharedMemorySize, SMEM_SZ);
    cudaFuncSetAttribute(k_xglb_tc, cudaFuncAttributeMaxDynamicSharedMemorySize, SMEM_SZ);
    cudaFuncSetAttribute(k_adj_tc, cudaFuncAttributeMaxDynamicSharedMemorySize, SMEM_SZ);
    cudaFuncSetAttribute(k_y1_tc, cudaFuncAttributeMaxDynamicSharedMemorySize, SMEM_SZ);
    cudaFuncSetAttribute(k_y2_tc, cudaFuncAttributeMaxDynamicSharedMemorySize, SMEM_SZ);

    k_cvt<<<1024, 256>>>(w_adj, w_dyn, x);
    k_energy_tc<<<dim3(KSPLIT, B_), 256, SMEM_SZ>>>();
    k_softmax<<<256, 128>>>();
    k_xglb_tc<<<dim3(N_ / 128, B_), 256, SMEM_SZ>>>(x, gamma);
    k_adj_tc<<<dim3(N_ / 128, N_ / 128, B_), 256, SMEM_SZ>>>(b_adj);
    k_y1_tc<<<dim3(N_ / 128, B_), 256, SMEM_SZ>>>();
    k_y2_tc<<<dim3(N_ / 128, B_), 256, SMEM_SZ>>>(b_dyn, out);
}

// round 9
// speedup vs baseline: 3.2522x; 1.2671x over previous
#include <cuda_runtime.h>
#include <cuda_fp16.h>
#include <cstdint>
#include <math.h>

#define B_ 8
#define C_ 128
#define N_ 2048
#define K2C 256
#define KSPLIT 16
#define SLOPE 0.2f

typedef unsigned int u32;
typedef unsigned long long u64;
typedef __half f16;

// ---------------- device scratch (allocation-free) ----------------
__device__ float g_epart[KSPLIT * B_ * C_ * C_];              // energy partials
__device__ f16 g_xcH[B_ * K2C * N_], g_xcL[B_ * K2C * N_];    // xc = [x_glb; x]
__device__ f16 g_wadjH[N_ * K2C], g_wadjL[N_ * K2C];
__device__ f16 g_wdynH[C_ * C_], g_wdynL[C_ * C_];
__device__ f16 g_attH[B_ * C_ * C_], g_attL[B_ * C_ * C_];
__device__ f16 g_adjH[(size_t)B_ * N_ * N_];                  // H only (B-side)
__device__ f16 g_y1H[B_ * C_ * N_];                           // H only (B-side)

// ---------------- primitives ----------------
__device__ __forceinline__ u32 smem_u32(const void* p) {
    u32 a;
    asm("{ .reg .u64 t; cvta.to.shared.u64 t, %1; cvt.u32.u64 %0, t; }"
        : "=r"(a) : "l"(p));
    return a;
}
__device__ __forceinline__ void ldsm4(u32* r, u32 addr) {
    asm volatile("ldmatrix.sync.aligned.m8n8.x4.shared.b16 {%0,%1,%2,%3}, [%4];"
                 : "=r"(r[0]), "=r"(r[1]), "=r"(r[2]), "=r"(r[3]) : "r"(addr));
}
__device__ __forceinline__ void ldsm4t(u32* r, u32 addr) {
    asm volatile("ldmatrix.sync.aligned.m8n8.x4.trans.shared.b16 {%0,%1,%2,%3}, [%4];"
                 : "=r"(r[0]), "=r"(r[1]), "=r"(r[2]), "=r"(r[3]) : "r"(addr));
}
__device__ __forceinline__ void mma_f16(float* c, const u32* a, const u32* b) {
    asm volatile(
        "mma.sync.aligned.m16n8k16.row.col.f32.f16.f16.f32 "
        "{%0,%1,%2,%3}, {%4,%5,%6,%7}, {%8,%9}, {%0,%1,%2,%3};"
        : "+f"(c[0]), "+f"(c[1]), "+f"(c[2]), "+f"(c[3])
        : "r"(a[0]), "r"(a[1]), "r"(a[2]), "r"(a[3]), "r"(b[0]), "r"(b[1]));
}
__device__ __forceinline__ void cpa16(u32 dst, const void* src) {
    asm volatile("cp.async.cg.shared.global [%0], [%1], 16;" :: "r"(dst), "l"(src));
}
#define CP_COMMIT() asm volatile("cp.async.commit_group;" ::: "memory")
#define CP_WAIT1() asm volatile("cp.async.wait_group 1;" ::: "memory")
#define CP_WAIT0() asm volatile("cp.async.wait_group 0;" ::: "memory")

#define SWZ(o) ((o) ^ (((o) >> 3) & 0x70))

// smem: A hi/lo single-buffered; B hi-only double-buffered
#define SM_AH 0
#define SM_AL 16384
#define SM_BH(buf) (32768 + (buf) * 16384)
#define SMEM_SZ 65536

__device__ __forceinline__ void split1(float v, f16& h, f16& l) {
    h = __float2half_rn(v);
    l = __float2half_rn(v - __half2float(h));
}
__device__ __forceinline__ u32 packh2(f16 a, f16 b) {
    return (u32)__half_as_ushort(a) | ((u32)__half_as_ushort(b) << 16);
}
__device__ __forceinline__ float leaky(float v) { return v > 0.0f ? v : SLOPE * v; }
__device__ __forceinline__ float sigm(float v) { return 1.0f / (1.0f + __expf(-v)); }

// Stage A-type tile (128 rows x 64 k) from f16 row-major src, SW128 swizzle.
__device__ __forceinline__ void stA(u32 sbase, const f16* __restrict__ src,
                                    int lda, int tid) {
    int row = tid & 127, g = tid >> 7;
    const f16* p = src + (size_t)row * lda + g * 32;
#pragma unroll
    for (int i = 0; i < 4; ++i) {
        int ch = g * 4 + i;
        cpa16(sbase + (u32)SWZ(row * 128 + ch * 16), p + i * 8);
    }
}
// Stage B-type tile (64 k rows x 128 n) from f16 [k][n] src, XOR chunk swizzle.
__device__ __forceinline__ void stB(u32 sbase, const f16* __restrict__ src,
                                    int ldb, int tid) {
    int kr = tid >> 2, q = tid & 3;
    const f16* p = src + (size_t)kr * ldb + q * 32;
#pragma unroll
    for (int i = 0; i < 4; ++i) {
        int ch = q * 4 + i;
        cpa16(sbase + (u32)(kr * 256 + ((ch ^ (kr & 15)) & 15) * 16), p + i * 8);
    }
}

// One 64-k chunk. Warp tile 32(m) x 64(n).
// BTRANS=true: 2-pass (A hi/lo x B hi) with B via ldmatrix.trans.
// BTRANS=false (energy, B=A tile): 3-pass both-split.
template <bool BTRANS>
__device__ __forceinline__ void chunk_mma(u32 sAH, u32 sAL, u32 sBH,
                                          int wm, int wn, int lane,
                                          float acc[2][8][4]) {
#pragma unroll
    for (int s = 0; s < 4; ++s) {
        int k0 = s * 16;
        u32 ah[2][4], al[2][4];
        {
            int am = lane & 15, ak = k0 + (lane >> 4) * 8;
            u32 o0 = (u32)SWZ((wm + am) * 128 + ak * 2);
            u32 o1 = (u32)SWZ((wm + 16 + am) * 128 + ak * 2);
            ldsm4(ah[0], sAH + o0);
            ldsm4(ah[1], sAH + o1);
            ldsm4(al[0], sAL + o0);
            ldsm4(al[1], sAL + o1);
        }
#pragma unroll
        for (int g = 0; g < 4; ++g) {
            if (BTRANS) {
                u32 bh[4];
                int t = lane >> 3, r = lane & 7;
                int k = k0 + (t & 1) * 8 + r;
                int nc = ((wn + g * 16) >> 3) + (t >> 1);
                u32 boff = (u32)(k * 256 + ((nc ^ (k & 15)) & 15) * 16);
                ldsm4t(bh, sBH + boff);
#pragma unroll
                for (int mf = 0; mf < 2; ++mf)
#pragma unroll
                    for (int nf = 0; nf < 2; ++nf) {
                        float* c = acc[mf][g * 2 + nf];
                        mma_f16(c, ah[mf], bh + nf * 2);
                        mma_f16(c, al[mf], bh + nf * 2);
                    }
            } else {
                u32 bh[4], bl[4];
                int t = lane >> 3, r = lane & 7;
                int n = wn + g * 16 + (t >> 1) * 8 + r;
                int k = k0 + (t & 1) * 8;
                u32 boff = (u32)SWZ(n * 128 + k * 2);
                ldsm4(bh, sAH + boff);
                ldsm4(bl, sAL + boff);
#pragma unroll
                for (int mf = 0; mf < 2; ++mf)
#pragma unroll
                    for (int nf = 0; nf < 2; ++nf) {
                        float* c = acc[mf][g * 2 + nf];
                        mma_f16(c, ah[mf], bh + nf * 2);
                        mma_f16(c, ah[mf], bl + nf * 2);
                        mma_f16(c, al[mf], bh + nf * 2);
                    }
            }
        }
    }
}

// Pipelined mainloop: A staged one chunk ahead, B double-buffered two ahead.
template <bool BTRANS>
__device__ __forceinline__ void gemm_main(u32 sb, const f16* aH, const f16* aL,
                                          int lda, const f16* bH, int ldb,
                                          int nc_total, int tid, int wm, int wn,
                                          int lane, float acc[2][8][4]) {
    if (BTRANS) {
        stA(sb + SM_AH, aH, lda, tid);
        stA(sb + SM_AL, aL, lda, tid);
        stB(sb + SM_BH(0), bH, ldb, tid);
        CP_COMMIT();
        if (nc_total > 1) {
            stB(sb + SM_BH(1), bH + (size_t)64 * ldb, ldb, tid);
            CP_COMMIT();
        }
#pragma unroll 1
        for (int kc = 0; kc < nc_total; ++kc) {
            if (kc + 1 < nc_total) CP_WAIT1(); else CP_WAIT0();
            __syncthreads();
            int cb = kc & 1;
            chunk_mma<true>(sb + SM_AH, sb + SM_AL, sb + SM_BH(cb), wm, wn, lane,
                            acc);
            __syncthreads();
            if (kc + 1 < nc_total) {
                stA(sb + SM_AH, aH + (size_t)(kc + 1) * 64, lda, tid);
                stA(sb + SM_AL, aL + (size_t)(kc + 1) * 64, lda, tid);
                CP_COMMIT();
            }
            if (kc + 2 < nc_total) {
                stB(sb + SM_BH(cb), bH + (size_t)(kc + 2) * 64 * ldb, ldb, tid);
                CP_COMMIT();
            }
        }
    } else {
#pragma unroll 1
        for (int kc = 0; kc < nc_total; ++kc) {
            stA(sb + SM_AH, aH + (size_t)kc * 64, lda, tid);
            stA(sb + SM_AL, aL + (size_t)kc * 64, lda, tid);
            CP_COMMIT();
            CP_WAIT0();
            __syncthreads();
            chunk_mma<false>(sb + SM_AH, sb + SM_AL, 0, wm, wn, lane, acc);
            __syncthreads();
        }
    }
}

// ---------------- pre-pass: convert weights + x to f16 hi/lo -----------------
__global__ void k_cvt(const float* __restrict__ w_adj,
                      const float* __restrict__ w_dyn,
                      const float* __restrict__ x) {
    int i0 = blockIdx.x * blockDim.x + threadIdx.x;
    int st = gridDim.x * blockDim.x;
    f16 h, l;
    for (int i = i0; i < N_ * K2C; i += st) {
        split1(w_adj[i], h, l);
        g_wadjH[i] = h;
        g_wadjL[i] = l;
    }
    for (int i = i0; i < C_ * C_; i += st) {
        split1(w_dyn[i], h, l);
        g_wdynH[i] = h;
        g_wdynL[i] = l;
    }
    for (int i = i0; i < B_ * C_ * N_; i += st) {
        int b = i / (C_ * N_);
        int rem = i - b * C_ * N_;
        size_t dst = (size_t)b * K2C * N_ + 128 * N_ + rem;  // xc rows 128..255 = x
        split1(x[i], h, l);
        g_xcH[dst] = h;
        g_xcL[dst] = l;
    }
}

// ---------------- energy partials: E_part[ks][b] = x_ks @ x_ks^T (3-pass) ----
__global__ void __launch_bounds__(256, 2) k_energy_tc() {
    extern __shared__ __align__(1024) char sm[];
    u32 sb = smem_u32(sm);
    int tid = threadIdx.x, wid = tid >> 5, lane = tid & 31;
    int wm = (wid >> 1) * 32, wn = (wid & 1) * 64;
    int ks = blockIdx.x, b = blockIdx.y;
    const f16* aH = g_xcH + ((size_t)b * K2C + 128) * N_ + ks * 128;
    const f16* aL = g_xcL + ((size_t)b * K2C + 128) * N_ + ks * 128;
    float acc[2][8][4] = {};
    gemm_main<false>(sb, aH, aL, N_, nullptr, 0, 2, tid, wm, wn, lane, acc);
    float* out = g_epart + ((size_t)(ks * B_ + b) * C_) * C_;
#pragma unroll
    for (int mf = 0; mf < 2; ++mf) {
        int r = wm + mf * 16 + (lane >> 2);
#pragma unroll
        for (int nf = 0; nf < 8; ++nf) {
            int c = wn + nf * 8 + (lane & 3) * 2;
            const float* a = acc[mf][nf];
            *reinterpret_cast<float2*>(out + r * C_ + c) = make_float2(a[0], a[1]);
            *reinterpret_cast<float2*>(out + (r + 8) * C_ + c) = make_float2(a[2], a[3]);
        }
    }
}

// ---------------- softmax(-energy) -> att f16 hi/lo --------------------------
__global__ void __launch_bounds__(128) k_softmax() {
    int warp = threadIdx.x >> 5, lane = threadIdx.x & 31;
    int row = blockIdx.x * 4 + warp;
    int b = row >> 7, c = row & 127;
    float e[4];
#pragma unroll
    for (int q = 0; q < 4; ++q) {
        int d = lane + q * 32;
        float s = 0.0f;
#pragma unroll
        for (int p = 0; p < KSPLIT; ++p)
            s += g_epart[((p * B_ + b) * C_ + c) * C_ + d];
        e[q] = -s;
    }
    float m = fmaxf(fmaxf(e[0], e[1]), fmaxf(e[2], e[3]));
#pragma unroll
    for (int off = 16; off > 0; off >>= 1)
        m = fmaxf(m, __shfl_xor_sync(0xffffffffu, m, off));
    float p4[4], s = 0.0f;
#pragma unroll
    for (int q = 0; q < 4; ++q) {
        p4[q] = __expf(e[q] - m);
        s += p4[q];
    }
#pragma unroll
    for (int off = 16; off > 0; off >>= 1)
        s += __shfl_xor_sync(0xffffffffu, s, off);
    float inv = 1.0f / s;
#pragma unroll
    for (int q = 0; q < 4; ++q) {
        f16 h, l;
        split1(p4[q] * inv, h, l);
        g_attH[(b * C_ + c) * C_ + lane + q * 32] = h;
        g_attL[(b * C_ + c) * C_ + lane + q * 32] = l;
    }
}

// ---------------- x_glb = gamma*(att @ x) + x -> xc rows 0..127 --------------
__global__ void __launch_bounds__(256, 2) k_xglb_tc(const float* __restrict__ x,
                                                    const float* __restrict__ gamma) {
    extern __shared__ __align__(1024) char sm[];
    u32 sb = smem_u32(sm);
    int tid = threadIdx.x, wid = tid >> 5, lane = tid & 31;
    int wm = (wid >> 1) * 32, wn = (wid & 1) * 64;
    int n0 = blockIdx.x * 128, b = blockIdx.y;
    const f16* aH = g_attH + (size_t)b * C_ * C_;
    const f16* aL = g_attL + (size_t)b * C_ * C_;
    const f16* bH = g_xcH + ((size_t)b * K2C + 128) * N_ + n0;
    float acc[2][8][4] = {};
    gemm_main<true>(sb, aH, aL, C_, bH, N_, 2, tid, wm, wn, lane, acc);
    float gm = *gamma;
    const float* xb = x + (size_t)b * C_ * N_;
    f16* oH = g_xcH + (size_t)b * K2C * N_;
    f16* oL = g_xcL + (size_t)b * K2C * N_;
#pragma unroll
    for (int mf = 0; mf < 2; ++mf) {
        int r = wm + mf * 16 + (lane >> 2);
#pragma unroll
        for (int nf = 0; nf < 8; ++nf) {
            int c = wn + nf * 8 + (lane & 3) * 2;
            const float* a = acc[mf][nf];
#pragma unroll
            for (int hrow = 0; hrow < 2; ++hrow) {
                int rr = r + hrow * 8;
                float v0 = fmaf(gm, a[hrow * 2 + 0], xb[(size_t)rr * N_ + n0 + c]);
                float v1 = fmaf(gm, a[hrow * 2 + 1], xb[(size_t)rr * N_ + n0 + c + 1]);
                f16 h0, l0, h1, l1;
                split1(v0, h0, l0);
                split1(v1, h1, l1);
                *reinterpret_cast<u32*>(oH + (size_t)rr * N_ + n0 + c) = packh2(h0, h1);
                *reinterpret_cast<u32*>(oL + (size_t)rr * N_ + n0 + c) = packh2(l0, l1);
            }
        }
    }
}

// ---------------- adj = sigmoid(w_adj @ xc + b_adj) -> f16 H only ------------
__global__ void __launch_bounds__(256, 2) k_adj_tc(const float* __restrict__ b_adj) {
    extern __shared__ __align__(1024) char sm[];
    u32 sb = smem_u32(sm);
    int tid = threadIdx.x, wid = tid >> 5, lane = tid & 31;
    int wm = (wid >> 1) * 32, wn = (wid & 1) * 64;
    int n0 = blockIdx.x * 128, m0 = blockIdx.y * 128, b = blockIdx.z;
    const f16* aH = g_wadjH + (size_t)m0 * K2C;
    const f16* aL = g_wadjL + (size_t)m0 * K2C;
    const f16* bH = g_xcH + (size_t)b * K2C * N_ + n0;
    float acc[2][8][4] = {};
    gemm_main<true>(sb, aH, aL, K2C, bH, N_, 4, tid, wm, wn, lane, acc);
    f16* oH = g_adjH + (size_t)b * N_ * N_;
#pragma unroll
    for (int mf = 0; mf < 2; ++mf) {
        int r = wm + mf * 16 + (lane >> 2);
#pragma unroll
        for (int nf = 0; nf < 8; ++nf) {
            int c = wn + nf * 8 + (lane & 3) * 2;
            const float* a = acc[mf][nf];
#pragma unroll
            for (int hrow = 0; hrow < 2; ++hrow) {
                int rr = r + hrow * 8;
                float bias = b_adj[m0 + rr];
                f16 h0 = __float2half_rn(sigm(a[hrow * 2 + 0] + bias));
                f16 h1 = __float2half_rn(sigm(a[hrow * 2 + 1] + bias));
                *reinterpret_cast<u32*>(oH + (size_t)(m0 + rr) * N_ + n0 + c) =
                    packh2(h0, h1);
            }
        }
    }
}

// ---------------- y1 = leaky(x @ adj) -> f16 H only ---------------------------
__global__ void __launch_bounds__(256, 2) k_y1_tc() {
    extern __shared__ __align__(1024) char sm[];
    u32 sb = smem_u32(sm);
    int tid = threadIdx.x, wid = tid >> 5, lane = tid & 31;
    int wm = (wid >> 1) * 32, wn = (wid & 1) * 64;
    int n0 = blockIdx.x * 128, b = blockIdx.y;
    const f16* aH = g_xcH + ((size_t)b * K2C + 128) * N_;  // x rows, k contig
    const f16* aL = g_xcL + ((size_t)b * K2C + 128) * N_;
    const f16* bH = g_adjH + (size_t)b * N_ * N_ + n0;
    float acc[2][8][4] = {};
    gemm_main<true>(sb, aH, aL, N_, bH, N_, 32, tid, wm, wn, lane, acc);
    f16* oH = g_y1H + (size_t)b * C_ * N_;
#pragma unroll
    for (int mf = 0; mf < 2; ++mf) {
        int r = wm + mf * 16 + (lane >> 2);
#pragma unroll
        for (int nf = 0; nf < 8; ++nf) {
            int c = wn + nf * 8 + (lane & 3) * 2;
            const float* a = acc[mf][nf];
#pragma unroll
            for (int hrow = 0; hrow < 2; ++hrow) {
                int rr = r + hrow * 8;
                f16 h0 = __float2half_rn(leaky(a[hrow * 2 + 0]));
                f16 h1 = __float2half_rn(leaky(a[hrow * 2 + 1]));
                *reinterpret_cast<u32*>(oH + (size_t)rr * N_ + n0 + c) =
                    packh2(h0, h1);
            }
        }
    }
}

// ---------------- y = leaky(w_dyn @ y1 + b_dyn) -> out f32 -------------------
__global__ void __launch_bounds__(256, 2) k_y2_tc(const float* __restrict__ b_dyn,
                                                  float* __restrict__ out) {
    extern __shared__ __align__(1024) char sm[];
    u32 sb = smem_u32(sm);
    int tid = threadIdx.x, wid = tid >> 5, lane = tid & 31;
    int wm = (wid >> 1) * 32, wn = (wid & 1) * 64;
    int n0 = blockIdx.x * 128, b = blockIdx.y;
    const f16* bH = g_y1H + (size_t)b * C_ * N_ + n0;
    float acc[2][8][4] = {};
    gemm_main<true>(sb, g_wdynH, g_wdynL, C_, bH, N_, 2, tid, wm, wn, lane, acc);
    float* ob = out + (size_t)b * C_ * N_;
#pragma unroll
    for (int mf = 0; mf < 2; ++mf) {
        int r = wm + mf * 16 + (lane >> 2);
#pragma unroll
        for (int nf = 0; nf < 8; ++nf) {
            int c = wn + nf * 8 + (lane & 3) * 2;
            const float* a = acc[mf][nf];
#pragma unroll
            for (int hrow = 0; hrow < 2; ++hrow) {
                int rr = r + hrow * 8;
                float bias = b_dyn[rr];
                *reinterpret_cast<float2*>(ob + (size_t)rr * N_ + n0 + c) =
                    make_float2(leaky(a[hrow * 2 + 0] + bias),
                                leaky(a[hrow * 2 + 1] + bias));
            }
        }
    }
}

// ---------------- launch ----------------
extern "C" void kernel_launch(void* const* d_in, const int* in_sizes, int n_in,
                              void* d_out, int out_size) {
    const float* x     = (const float*)d_in[0];  // [8,128,2048]
    const float* w_adj = (const float*)d_in[1];  // [2048,256]
    const float* b_adj = (const float*)d_in[2];  // [2048]
    const float* w_dyn = (const float*)d_in[3];  // [128,128]
    const float* b_dyn = (const float*)d_in[4];  // [128]
    const float* gamma = (const float*)d_in[5];  // [1]
    float* out = (float*)d_out;                  // [8,128,2048]

    cudaFuncSetAttribute(k_energy_tc, cudaFuncAttributeMaxDynamicSharedMemorySize, SMEM_SZ);
    cudaFuncSetAttribute(k_xglb_tc, cudaFuncAttributeMaxDynamicSharedMemorySize, SMEM_SZ);
    cudaFuncSetAttribute(k_adj_tc, cudaFuncAttributeMaxDynamicSharedMemorySize, SMEM_SZ);
    cudaFuncSetAttribute(k_y1_tc, cudaFuncAttributeMaxDynamicSharedMemorySize, SMEM_SZ);
    cudaFuncSetAttribute(k_y2_tc, cudaFuncAttributeMaxDynamicSharedMemorySize, SMEM_SZ);

    k_cvt<<<1024, 256>>>(w_adj, w_dyn, x);
    k_energy_tc<<<dim3(KSPLIT, B_), 256, SMEM_SZ>>>();
    k_softmax<<<256, 128>>>();
    k_xglb_tc<<<dim3(N_ / 128, B_), 256, SMEM_SZ>>>(x, gamma);
    k_adj_tc<<<dim3(N_ / 128, N_ / 128, B_), 256, SMEM_SZ>>>(b_adj);
    k_y1_tc<<<dim3(N_ / 128, B_), 256, SMEM_SZ>>>();
    k_y2_tc<<<dim3(N_ / 128, B_), 256, SMEM_SZ>>>(b_dyn, out);
}